// round 1
// baseline (speedup 1.0000x reference)
#include <cuda_runtime.h>
#include <math.h>

#define Bsz 16
#define Ssz 1024
#define Hsz 768
#define NHs 12
#define Dh  64
#define FFs 3072

// ---------------- scratch (device globals; no allocation) ----------------
__device__ float d_q0[Bsz*Hsz];
__device__ float d_qbk[Bsz*NHs];
__device__ float d_u[Bsz*NHs*Hsz];            // prescaled by 1/8
__device__ float d_scores[Bsz*NHs*Ssz];       // scores -> probs in place
__device__ float d_fbar_part[8*Bsz*NHs*Hsz];
__device__ float d_fbar[Bsz*NHs*Hsz];
__device__ float d_attn0[Bsz*Hsz];
__device__ float d_gpart[4*Bsz*FFs];
__device__ float d_g[Bsz*FFs];
__device__ float d_opart[8*Bsz*Hsz];

// ---------------- block reductions ----------------
__device__ __forceinline__ float block_sum(float v, float* red){
  int lane = threadIdx.x & 31, w = threadIdx.x >> 5, nw = blockDim.x >> 5;
  #pragma unroll
  for (int o = 16; o; o >>= 1) v += __shfl_xor_sync(0xffffffffu, v, o);
  if (lane == 0) red[w] = v;
  __syncthreads();
  float s = (lane < nw) ? red[lane] : 0.f;
  #pragma unroll
  for (int o = 16; o; o >>= 1) s += __shfl_xor_sync(0xffffffffu, s, o);
  __syncthreads();
  return s;
}
__device__ __forceinline__ float block_max(float v, float* red){
  int lane = threadIdx.x & 31, w = threadIdx.x >> 5, nw = blockDim.x >> 5;
  #pragma unroll
  for (int o = 16; o; o >>= 1) v = fmaxf(v, __shfl_xor_sync(0xffffffffu, v, o));
  if (lane == 0) red[w] = v;
  __syncthreads();
  float s = (lane < nw) ? red[lane] : -INFINITY;
  #pragma unroll
  for (int o = 16; o; o >>= 1) s = fmaxf(s, __shfl_xor_sync(0xffffffffu, s, o));
  __syncthreads();
  return s;
}

// ---------------- q0 = features[:,0,:] @ wq + bq ----------------
__global__ void k_q0(const float* __restrict__ f, const float* __restrict__ wq,
                     const float* __restrict__ bq){
  int b = blockIdx.x;
  __shared__ float fs[Hsz];
  for (int i = threadIdx.x; i < Hsz; i += blockDim.x)
    fs[i] = f[(size_t)b*Ssz*Hsz + i];
  __syncthreads();
  for (int j = threadIdx.x; j < Hsz; j += blockDim.x){
    float a0 = bq[j], a1 = 0.f;
    #pragma unroll 8
    for (int i = 0; i < Hsz; i += 2){
      a0 = fmaf(fs[i],   wq[(size_t)i*Hsz + j],     a0);
      a1 = fmaf(fs[i+1], wq[(size_t)(i+1)*Hsz + j], a1);
    }
    d_q0[b*Hsz + j] = a0 + a1;
  }
}

// ---------------- u[b,h] = (Wk_h @ q0[b,h]) / 8 ; qbk = (q0 . bk_h)/8 ----
__global__ void k_u(const float* __restrict__ wk, const float* __restrict__ bk){
  int h = blockIdx.x, b = blockIdx.y;
  __shared__ __align__(16) float qs[Dh];
  int t = threadIdx.x;
  if (t < Dh) qs[t] = d_q0[b*Hsz + h*Dh + t];
  __syncthreads();
  if (t == 0){
    float s = 0.f;
    for (int d = 0; d < Dh; d++) s += qs[d]*bk[h*Dh + d];
    d_qbk[b*NHs + h] = s * 0.125f;
  }
  for (int i = t; i < Hsz; i += blockDim.x){
    const float4* wr = reinterpret_cast<const float4*>(wk + (size_t)i*Hsz + h*Dh);
    const float4* q4 = reinterpret_cast<const float4*>(qs);
    float acc = 0.f;
    #pragma unroll
    for (int d = 0; d < Dh/4; d++){
      float4 w = wr[d]; float4 q = q4[d];
      acc += w.x*q.x + w.y*q.y + w.z*q.z + w.w*q.w;
    }
    d_u[(b*NHs + h)*Hsz + i] = acc * 0.125f;
  }
}

// ---------------- pass 1: scores[b,h,s] = f[b,s].u[b,h] + qbk + mask ------
// block: 256 threads, 64 rows, 4 threads/row (i-quarters), grid (16 schunk, 16 b)
__global__ void k_scores(const float* __restrict__ f, const float* __restrict__ mask){
  int b = blockIdx.y, s0 = blockIdx.x * 64;
  int t = threadIdx.x;
  int r = t >> 2, q = t & 3;
  __shared__ float fs[64*33];
  __shared__ __align__(16) float us[NHs*32];
  float acc[NHs];
  #pragma unroll
  for (int h = 0; h < NHs; h++) acc[h] = 0.f;
  const float* fbase = f + ((size_t)b*Ssz + s0)*Hsz;
  const float* ubase = d_u + (size_t)b*NHs*Hsz;

  for (int ic = 0; ic < Hsz/32; ic++){
    __syncthreads();
    #pragma unroll
    for (int k = 0; k < 8; k++){
      int n = t + 256*k;
      fs[(n>>5)*33 + (n&31)] = fbase[(size_t)(n>>5)*Hsz + ic*32 + (n&31)];
    }
    {
      int n = t;
      us[n] = ubase[(n>>5)*Hsz + ic*32 + (n&31)];
      if (t < 128){ int n2 = t + 256; us[n2] = ubase[(n2>>5)*Hsz + ic*32 + (n2&31)]; }
    }
    __syncthreads();
    #pragma unroll
    for (int g = 0; g < 2; g++){
      int i0 = q*8 + g*4;
      float f0 = fs[r*33+i0],   f1 = fs[r*33+i0+1];
      float f2 = fs[r*33+i0+2], f3 = fs[r*33+i0+3];
      #pragma unroll
      for (int h = 0; h < NHs; h++){
        float4 uu = *reinterpret_cast<const float4*>(&us[h*32 + i0]);
        acc[h] = fmaf(f0, uu.x, acc[h]);
        acc[h] = fmaf(f1, uu.y, acc[h]);
        acc[h] = fmaf(f2, uu.z, acc[h]);
        acc[h] = fmaf(f3, uu.w, acc[h]);
      }
    }
  }
  #pragma unroll
  for (int h = 0; h < NHs; h++){
    acc[h] += __shfl_xor_sync(0xffffffffu, acc[h], 1);
    acc[h] += __shfl_xor_sync(0xffffffffu, acc[h], 2);
  }
  if (q == 0){
    int srow = s0 + r;
    float m = mask[b*Ssz + srow];
    #pragma unroll
    for (int h = 0; h < NHs; h++)
      d_scores[(size_t)(b*NHs + h)*Ssz + srow] = acc[h] + d_qbk[b*NHs + h] + m;
  }
}

// ---------------- softmax over s per (b,h) row, in place -----------------
__global__ void k_softmax(){
  __shared__ float red[32];
  float* p = d_scores + (size_t)blockIdx.x * Ssz;
  int t = threadIdx.x;
  float v0 = p[t], v1 = p[t+256], v2 = p[t+512], v3 = p[t+768];
  float m = block_max(fmaxf(fmaxf(v0,v1), fmaxf(v2,v3)), red);
  v0 = expf(v0 - m); v1 = expf(v1 - m); v2 = expf(v2 - m); v3 = expf(v3 - m);
  float s = block_sum(v0+v1+v2+v3, red);
  float inv = 1.f / s;
  p[t] = v0*inv; p[t+256] = v1*inv; p[t+512] = v2*inv; p[t+768] = v3*inv;
}

// ---------------- pass 2: fbar partials over s-chunks --------------------
__global__ void __launch_bounds__(192) k_fbar_part(const float* __restrict__ f){
  int b = blockIdx.x, sc = blockIdx.y;
  int t = threadIdx.x; // 192
  __shared__ float ps[NHs*128];
  for (int n = t; n < NHs*128; n += 192)
    ps[n] = d_scores[(size_t)(b*NHs + (n>>7))*Ssz + sc*128 + (n&127)];
  __syncthreads();
  float acc[48];
  #pragma unroll
  for (int k = 0; k < 48; k++) acc[k] = 0.f;
  const float* fb = f + ((size_t)b*Ssz + sc*128)*Hsz + t*4;
  for (int s = 0; s < 128; s++){
    float4 ff = *reinterpret_cast<const float4*>(fb + (size_t)s*Hsz);
    #pragma unroll
    for (int h = 0; h < NHs; h++){
      float pp = ps[h*128 + s];
      acc[h*4+0] = fmaf(pp, ff.x, acc[h*4+0]);
      acc[h*4+1] = fmaf(pp, ff.y, acc[h*4+1]);
      acc[h*4+2] = fmaf(pp, ff.z, acc[h*4+2]);
      acc[h*4+3] = fmaf(pp, ff.w, acc[h*4+3]);
    }
  }
  #pragma unroll
  for (int h = 0; h < NHs; h++){
    float4 o = make_float4(acc[h*4], acc[h*4+1], acc[h*4+2], acc[h*4+3]);
    *reinterpret_cast<float4*>(&d_fbar_part[((size_t)(sc*Bsz + b)*NHs + h)*Hsz + t*4]) = o;
  }
}

__global__ void k_fbar_reduce(){
  int n = blockIdx.x*1024 + threadIdx.x;
  float s = 0.f;
  #pragma unroll
  for (int sc = 0; sc < 8; sc++) s += d_fbar_part[(size_t)sc*(Bsz*NHs*Hsz) + n];
  d_fbar[n] = s;
}

// ------------- ctx = fbar@Wv + bv ; y = ctx@wo + bo + f0 ; LN1 -----------
__global__ void k_ctx_attn(const float* __restrict__ wv, const float* __restrict__ bv,
                           const float* __restrict__ wo, const float* __restrict__ bo,
                           const float* __restrict__ f,
                           const float* __restrict__ g1, const float* __restrict__ be1){
  int b = blockIdx.x, j = threadIdx.x; // 768 threads
  __shared__ float fs[NHs*Hsz];
  __shared__ float cs[Hsz];
  __shared__ float red[32];
  for (int n = j; n < NHs*Hsz; n += Hsz) fs[n] = d_fbar[b*NHs*Hsz + n];
  __syncthreads();
  int h = j >> 6;
  const float* fh = fs + h*Hsz;
  float a0 = bv[j], a1 = 0.f;
  #pragma unroll 8
  for (int i = 0; i < Hsz; i += 2){
    a0 = fmaf(fh[i],   wv[(size_t)i*Hsz + j],     a0);
    a1 = fmaf(fh[i+1], wv[(size_t)(i+1)*Hsz + j], a1);
  }
  cs[j] = a0 + a1;
  __syncthreads();
  float y0 = bo[j] + f[(size_t)b*Ssz*Hsz + j], y1 = 0.f;
  #pragma unroll 8
  for (int i = 0; i < Hsz; i += 2){
    y0 = fmaf(cs[i],   wo[(size_t)i*Hsz + j],     y0);
    y1 = fmaf(cs[i+1], wo[(size_t)(i+1)*Hsz + j], y1);
  }
  float y = y0 + y1;
  float mu  = block_sum(y, red) * (1.f/Hsz);
  float d   = y - mu;
  float var = block_sum(d*d, red) * (1.f/Hsz);
  d_attn0[b*Hsz + j] = d * rsqrtf(var + 1e-12f) * g1[j] + be1[j];
}

// ---------------- FFN layer 1 partials: attn0 @ w1 ----------------------
__global__ void k_ffn1_part(const float* __restrict__ w1){
  int mc = blockIdx.x, is = blockIdx.y;
  int t = threadIdx.x; // 128
  int m = mc*128 + t;
  int i0 = is*192;
  __shared__ float as[Bsz*192];
  for (int n = t; n < Bsz*192; n += 128)
    as[n] = d_attn0[(n/192)*Hsz + i0 + (n%192)];
  __syncthreads();
  float acc[Bsz];
  #pragma unroll
  for (int k = 0; k < Bsz; k++) acc[k] = 0.f;
  for (int i = 0; i < 192; i++){
    float w = w1[(size_t)(i0 + i)*FFs + m];
    #pragma unroll
    for (int bb = 0; bb < Bsz; bb++) acc[bb] = fmaf(as[bb*192 + i], w, acc[bb]);
  }
  #pragma unroll
  for (int bb = 0; bb < Bsz; bb++)
    d_gpart[(size_t)(is*Bsz + bb)*FFs + m] = acc[bb];
}

// ---------------- reduce + exact GELU ----------------
__global__ void k_gelu(const float* __restrict__ b1){
  int n = blockIdx.x*256 + threadIdx.x; // < Bsz*FFs = 49152
  float s = b1[n % FFs];
  #pragma unroll
  for (int is = 0; is < 4; is++) s += d_gpart[(size_t)is*(Bsz*FFs) + n];
  d_g[n] = 0.5f * s * (1.f + erff(s * 0.70710678118654752f));
}

// ---------------- FFN layer 2 partials: g @ w2 ----------------
__global__ void k_ffn2_part(const float* __restrict__ w2){
  int jc = blockIdx.x, ms = blockIdx.y;
  int t = threadIdx.x; // 128
  int j = jc*128 + t;
  int m0 = ms*384;
  __shared__ float gs[Bsz*384];
  for (int n = t; n < Bsz*384; n += 128)
    gs[n] = d_g[(n/384)*FFs + m0 + (n%384)];
  __syncthreads();
  float acc[Bsz];
  #pragma unroll
  for (int k = 0; k < Bsz; k++) acc[k] = 0.f;
  for (int m = 0; m < 384; m++){
    float w = w2[(size_t)(m0 + m)*Hsz + j];
    #pragma unroll
    for (int bb = 0; bb < Bsz; bb++) acc[bb] = fmaf(gs[bb*384 + m], w, acc[bb]);
  }
  #pragma unroll
  for (int bb = 0; bb < Bsz; bb++)
    d_opart[(size_t)(ms*Bsz + bb)*Hsz + j] = acc[bb];
}

// ------------- LN2 -> pooled = tanh(hidden0@wp+bp) -> cls ---------------
__global__ void k_final(const float* __restrict__ b2, const float* __restrict__ g2,
                        const float* __restrict__ be2,
                        const float* __restrict__ wp, const float* __restrict__ bp,
                        const float* __restrict__ wm, const float* __restrict__ bm,
                        float* __restrict__ out){
  int b = blockIdx.x, j = threadIdx.x; // 768 threads
  __shared__ float hs[Hsz];
  __shared__ float red[32];
  float y = b2[j] + d_attn0[b*Hsz + j];
  #pragma unroll
  for (int ms = 0; ms < 8; ms++) y += d_opart[(size_t)(ms*Bsz + b)*Hsz + j];
  float mu  = block_sum(y, red) * (1.f/Hsz);
  float d   = y - mu;
  float var = block_sum(d*d, red) * (1.f/Hsz);
  hs[j] = d * rsqrtf(var + 1e-12f) * g2[j] + be2[j];
  __syncthreads();
  float p0 = bp[j], p1 = 0.f;
  #pragma unroll 8
  for (int i = 0; i < Hsz; i += 2){
    p0 = fmaf(hs[i],   wp[(size_t)i*Hsz + j],     p0);
    p1 = fmaf(hs[i+1], wp[(size_t)(i+1)*Hsz + j], p1);
  }
  float pj = tanhf(p0 + p1);
  float c = block_sum(pj * wm[j], red);
  if (j == 0) out[b] = c + bm[0];
}

// ---------------- launch ----------------
extern "C" void kernel_launch(void* const* d_in, const int* in_sizes, int n_in,
                              void* d_out, int out_size){
  (void)in_sizes; (void)n_in; (void)out_size;
  const float* features = (const float*)d_in[0];
  const float* mask     = (const float*)d_in[1];
  const float* wq  = (const float*)d_in[2];
  const float* bq  = (const float*)d_in[3];
  const float* wk  = (const float*)d_in[4];
  const float* bk  = (const float*)d_in[5];
  const float* wv  = (const float*)d_in[6];
  const float* bv  = (const float*)d_in[7];
  const float* wo  = (const float*)d_in[8];
  const float* bo  = (const float*)d_in[9];
  const float* ln1g = (const float*)d_in[10];
  const float* ln1b = (const float*)d_in[11];
  const float* w1  = (const float*)d_in[12];
  const float* b1  = (const float*)d_in[13];
  const float* w2  = (const float*)d_in[14];
  const float* b2  = (const float*)d_in[15];
  const float* ln2g = (const float*)d_in[16];
  const float* ln2b = (const float*)d_in[17];
  const float* wp  = (const float*)d_in[18];
  const float* bp  = (const float*)d_in[19];
  const float* wm  = (const float*)d_in[20];
  const float* bm  = (const float*)d_in[21];
  float* out = (float*)d_out;

  k_q0<<<Bsz, 256>>>(features, wq, bq);
  k_u<<<dim3(NHs, Bsz), 256>>>(wk, bk);
  k_scores<<<dim3(16, Bsz), 256>>>(features, mask);
  k_softmax<<<Bsz*NHs, 256>>>();
  k_fbar_part<<<dim3(Bsz, 8), 192>>>(features);
  k_fbar_reduce<<<144, 1024>>>();
  k_ctx_attn<<<Bsz, Hsz>>>(wv, bv, wo, bo, features, ln1g, ln1b);
  k_ffn1_part<<<dim3(24, 4), 128>>>(w1);
  k_gelu<<<192, 256>>>(b1);
  k_ffn2_part<<<dim3(6, 8), 128>>>(w2);
  k_final<<<Bsz, Hsz>>>(b2, ln2g, ln2b, wp, bp, wm, bm, out);
}

// round 2
// speedup vs baseline: 2.3126x; 2.3126x over previous
#include <cuda_runtime.h>
#include <math.h>

#define Bsz 16
#define Ssz 1024
#define Hsz 768
#define NHs 12
#define Dh  64
#define FFs 3072

// ---------------- scratch (device globals; no allocation) ----------------
__device__ float d_q0p[12*Bsz*Hsz];
__device__ float d_u[Bsz*NHs*Hsz];            // prescaled by 1/8
__device__ float d_qbk[Bsz*NHs];
__device__ float d_scores[Bsz*NHs*Ssz];       // scores -> probs in place
__device__ float d_fbp[16*Bsz*NHs*Hsz];       // fbar partials over 16 s-chunks
__device__ float d_ctxp[12*Bsz*Hsz];
__device__ float d_yp[12*Bsz*Hsz];
__device__ float d_attn0[Bsz*Hsz];
__device__ float d_gpart[8*Bsz*FFs];
__device__ float d_g[Bsz*FFs];
__device__ float d_opart[24*Bsz*Hsz];
__device__ float d_hid[Bsz*Hsz];
__device__ float d_pp[12*Bsz*Hsz];

typedef unsigned long long ull;

// ---------------- f32x2 packed math helpers ----------------
__device__ __forceinline__ ull ffma2(ull a, ull b, ull c){
  ull d; asm("fma.rn.f32x2 %0, %1, %2, %3;" : "=l"(d) : "l"(a), "l"(b), "l"(c)); return d;
}
__device__ __forceinline__ ull pk2(float lo, float hi){
  ull r; asm("mov.b64 %0, {%1, %2};" : "=l"(r) : "f"(lo), "f"(hi)); return r;
}
__device__ __forceinline__ void upk2(float& lo, float& hi, ull v){
  asm("mov.b64 {%0, %1}, %2;" : "=f"(lo), "=f"(hi) : "l"(v));
}

// ---------------- block reductions ----------------
__device__ __forceinline__ float block_sum(float v, float* red){
  int lane = threadIdx.x & 31, w = threadIdx.x >> 5, nw = blockDim.x >> 5;
  #pragma unroll
  for (int o = 16; o; o >>= 1) v += __shfl_xor_sync(0xffffffffu, v, o);
  if (lane == 0) red[w] = v;
  __syncthreads();
  float s = (lane < nw) ? red[lane] : 0.f;
  #pragma unroll
  for (int o = 16; o; o >>= 1) s += __shfl_xor_sync(0xffffffffu, s, o);
  __syncthreads();
  return s;
}
__device__ __forceinline__ float block_max(float v, float* red){
  int lane = threadIdx.x & 31, w = threadIdx.x >> 5, nw = blockDim.x >> 5;
  #pragma unroll
  for (int o = 16; o; o >>= 1) v = fmaxf(v, __shfl_xor_sync(0xffffffffu, v, o));
  if (lane == 0) red[w] = v;
  __syncthreads();
  float s = (lane < nw) ? red[lane] : -INFINITY;
  #pragma unroll
  for (int o = 16; o; o >>= 1) s = fmaxf(s, __shfl_xor_sync(0xffffffffu, s, o));
  __syncthreads();
  return s;
}

// ============ q0 partials: q0[b,j] = f0[b,:] @ wq + bq (K-split 12) ============
__global__ void k_q0p(const float* __restrict__ f, const float* __restrict__ wq,
                      const float* __restrict__ bq){
  int jc = blockIdx.x, ks = blockIdx.y;            // 6 x 12
  int t = threadIdx.x;                              // 256
  int j0 = jc*128, i0 = ks*64;
  __shared__ float f0s[Bsz*64];
  #pragma unroll
  for (int k = 0; k < 4; k++){
    int v = t + 256*k;
    f0s[v] = f[(size_t)(v>>6)*Ssz*Hsz + i0 + (v&63)];
  }
  __syncthreads();
  int j = j0 + (t & 127), bh = t >> 7;
  float acc[8];
  float binit = (ks == 0) ? bq[j] : 0.f;
  #pragma unroll
  for (int bb = 0; bb < 8; bb++) acc[bb] = binit * ((bb==0)?1.f:1.f); // same bias for all b
  #pragma unroll
  for (int bb = 0; bb < 8; bb++) acc[bb] = binit;
  #pragma unroll 4
  for (int i = 0; i < 64; i++){
    float w = wq[(size_t)(i0+i)*Hsz + j];
    #pragma unroll
    for (int bb = 0; bb < 8; bb++)
      acc[bb] = fmaf(f0s[(bh*8+bb)*64 + i], w, acc[bb]);
  }
  #pragma unroll
  for (int bb = 0; bb < 8; bb++)
    d_q0p[ks*(Bsz*Hsz) + (bh*8+bb)*Hsz + j] = acc[bb];
}

// ============ u[b,h,i] = Wk_h q0[b,h] / 8 ; qbk[b,h] = q0.bk_h / 8 ============
__global__ void k_u(const float* __restrict__ wk, const float* __restrict__ bk){
  int h = blockIdx.x, ic = blockIdx.y;              // 12 x 6
  int t = threadIdx.x;                              // 256
  __shared__ __align__(16) float q0s[Bsz*Dh];
  #pragma unroll
  for (int k = 0; k < 4; k++){
    int v = t + 256*k;                              // b*64+d
    float s = 0.f;
    #pragma unroll
    for (int p = 0; p < 12; p++)
      s += d_q0p[p*(Bsz*Hsz) + (v>>6)*Hsz + h*Dh + (v&63)];
    q0s[v] = s;
  }
  __syncthreads();
  if (t < Bsz){
    float s = 0.f;
    for (int d = 0; d < Dh; d++) s += q0s[t*Dh + d]*bk[h*Dh + d];
    d_qbk[t*NHs + h] = s * 0.125f;
  }
  int i = ic*128 + (t & 127), bh = t >> 7;
  const float4* wr = reinterpret_cast<const float4*>(wk + (size_t)i*Hsz + h*Dh);
  float acc[8] = {0,0,0,0,0,0,0,0};
  #pragma unroll
  for (int d4 = 0; d4 < Dh/4; d4++){
    float4 w = wr[d4];
    #pragma unroll
    for (int bb = 0; bb < 8; bb++){
      float4 q = *reinterpret_cast<const float4*>(&q0s[(bh*8+bb)*Dh + d4*4]);
      acc[bb] = fmaf(w.x,q.x, fmaf(w.y,q.y, fmaf(w.z,q.z, fmaf(w.w,q.w, acc[bb]))));
    }
  }
  #pragma unroll
  for (int bb = 0; bb < 8; bb++)
    d_u[((bh*8+bb)*NHs + h)*Hsz + i] = acc[bb] * 0.125f;
}

// ============ pass 1: scores[b,h,s] = f[b,s,:].u[b,h,:] + qbk + mask ============
// 256 thr: r = s-row (64), q = i-quarter (4). f read direct from global (float4).
__global__ void k_scores(const float* __restrict__ f, const float* __restrict__ mask){
  int sc = blockIdx.x, b = blockIdx.y;              // 16 x 16
  int t = threadIdx.x;
  int r = t >> 2, q = t & 3;
  __shared__ __align__(16) float us[NHs*32];
  ull acc2[NHs];
  #pragma unroll
  for (int h = 0; h < NHs; h++) acc2[h] = 0ull;
  const float* fbase = f + ((size_t)b*Ssz + sc*64)*Hsz;
  const float* ubase = d_u + (size_t)b*NHs*Hsz;

  for (int ic = 0; ic < Hsz/32; ic++){
    __syncthreads();
    us[t] = ubase[(t>>5)*Hsz + ic*32 + (t&31)];
    if (t < 128){ int n = t + 256; us[n] = ubase[(n>>5)*Hsz + ic*32 + (n&31)]; }
    __syncthreads();
    #pragma unroll
    for (int g = 0; g < 2; g++){
      ulonglong2 fv = *reinterpret_cast<const ulonglong2*>(
          fbase + (size_t)r*Hsz + ic*32 + q*8 + g*4);
      #pragma unroll
      for (int h = 0; h < NHs; h++){
        ulonglong2 uv = *reinterpret_cast<const ulonglong2*>(&us[h*32 + q*8 + g*4]);
        acc2[h] = ffma2(fv.x, uv.x, acc2[h]);
        acc2[h] = ffma2(fv.y, uv.y, acc2[h]);
      }
    }
  }
  int srow = sc*64 + r;
  float m = mask[b*Ssz + srow];
  #pragma unroll
  for (int h = 0; h < NHs; h++){
    float lo, hi; upk2(lo, hi, acc2[h]);
    float v = lo + hi;
    v += __shfl_xor_sync(0xffffffffu, v, 1);
    v += __shfl_xor_sync(0xffffffffu, v, 2);
    if (q == 0)
      d_scores[(size_t)(b*NHs + h)*Ssz + srow] = v + d_qbk[b*NHs + h] + m;
  }
}

// ============ softmax over s per (b,h) row, in place ============
__global__ void k_softmax(){
  __shared__ float red[32];
  float* p = d_scores + (size_t)blockIdx.x * Ssz;
  int t = threadIdx.x;                              // 1024
  float v = p[t];
  float m = block_max(v, red);
  float e = expf(v - m);
  float s = block_sum(e, red);
  p[t] = e / s;
}

// ============ pass 2: fbar partials over 16 s-chunks (f32x2) ============
__global__ void __launch_bounds__(192) k_fbar(const float* __restrict__ f){
  int b = blockIdx.x, sc = blockIdx.y;              // 16 x 16
  int t = threadIdx.x;                              // 192
  __shared__ __align__(16) ull ps2[NHs*64];
  for (int n = t; n < NHs*64; n += 192){
    float pv = d_scores[(size_t)(b*NHs + (n>>6))*Ssz + sc*64 + (n&63)];
    ps2[n] = pk2(pv, pv);
  }
  __syncthreads();
  ull acc2[2*NHs];
  #pragma unroll
  for (int k = 0; k < 2*NHs; k++) acc2[k] = 0ull;
  const float* fb = f + ((size_t)b*Ssz + sc*64)*Hsz + t*4;
  for (int s = 0; s < 64; s++){
    ulonglong2 fv = *reinterpret_cast<const ulonglong2*>(fb + (size_t)s*Hsz);
    #pragma unroll
    for (int h = 0; h < NHs; h++){
      ull pp = ps2[h*64 + s];
      acc2[2*h]   = ffma2(pp, fv.x, acc2[2*h]);
      acc2[2*h+1] = ffma2(pp, fv.y, acc2[2*h+1]);
    }
  }
  #pragma unroll
  for (int h = 0; h < NHs; h++){
    float4 o;
    upk2(o.x, o.y, acc2[2*h]);
    upk2(o.z, o.w, acc2[2*h+1]);
    *reinterpret_cast<float4*>(
      &d_fbp[((size_t)(sc*Bsz + b)*NHs + h)*Hsz + t*4]) = o;
  }
}

// ============ ctx partials: ctx[b,j] = fbar[b,j>>6,:] @ wv[:,j] (K-split 12) ====
__global__ void k_ctxp(const float* __restrict__ wv){
  int jc = blockIdx.x, ks = blockIdx.y;             // 6 x 12
  int t = threadIdx.x;                              // 256
  int j0 = jc*128, i0 = ks*64, h0 = jc*2;
  __shared__ float As[Bsz*2*64];                    // [b][hl][i]
  #pragma unroll
  for (int k = 0; k < 8; k++){
    int v = t + 256*k;
    int bb = v>>7, hl = (v>>6)&1, i = v&63;
    float s = 0.f;
    #pragma unroll
    for (int sc = 0; sc < 16; sc++)
      s += d_fbp[((size_t)(sc*Bsz + bb)*NHs + h0 + hl)*Hsz + i0 + i];
    As[v] = s;
  }
  __syncthreads();
  int j = j0 + (t & 127), hl = (t & 127) >> 6, bh = t >> 7;
  float acc[8] = {0,0,0,0,0,0,0,0};
  #pragma unroll 4
  for (int i = 0; i < 64; i++){
    float w = wv[(size_t)(i0+i)*Hsz + j];
    #pragma unroll
    for (int bb = 0; bb < 8; bb++)
      acc[bb] = fmaf(As[(bh*8+bb)*128 + hl*64 + i], w, acc[bb]);
  }
  #pragma unroll
  for (int bb = 0; bb < 8; bb++)
    d_ctxp[ks*(Bsz*Hsz) + (bh*8+bb)*Hsz + j] = acc[bb];
}

// ============ y partials: y[b,j] = ctx[b,:] @ wo[:,j] (K-split 12) ============
__global__ void k_yp(const float* __restrict__ wo, const float* __restrict__ bv){
  int jc = blockIdx.x, ks = blockIdx.y;             // 6 x 12
  int t = threadIdx.x;                              // 256
  int j0 = jc*128, i0 = ks*64;
  __shared__ float Cs[Bsz*64];
  #pragma unroll
  for (int k = 0; k < 4; k++){
    int v = t + 256*k;
    int bb = v>>6, i = v&63;
    float s = bv[i0 + i];
    #pragma unroll
    for (int p = 0; p < 12; p++)
      s += d_ctxp[p*(Bsz*Hsz) + bb*Hsz + i0 + i];
    Cs[v] = s;
  }
  __syncthreads();
  int j = j0 + (t & 127), bh = t >> 7;
  float acc[8] = {0,0,0,0,0,0,0,0};
  #pragma unroll 4
  for (int i = 0; i < 64; i++){
    float w = wo[(size_t)(i0+i)*Hsz + j];
    #pragma unroll
    for (int bb = 0; bb < 8; bb++)
      acc[bb] = fmaf(Cs[(bh*8+bb)*64 + i], w, acc[bb]);
  }
  #pragma unroll
  for (int bb = 0; bb < 8; bb++)
    d_yp[ks*(Bsz*Hsz) + (bh*8+bb)*Hsz + j] = acc[bb];
}

// ============ LN1: attn0 = LN(y + bo + f0) ============
__global__ void k_ln1(const float* __restrict__ f, const float* __restrict__ bo,
                      const float* __restrict__ g1, const float* __restrict__ be1){
  int b = blockIdx.x, j = threadIdx.x;              // 16 x 768
  __shared__ float red[32];
  float y = bo[j] + f[(size_t)b*Ssz*Hsz + j];
  #pragma unroll
  for (int ks = 0; ks < 12; ks++) y += d_yp[ks*(Bsz*Hsz) + b*Hsz + j];
  float mu  = block_sum(y, red) * (1.f/Hsz);
  float d   = y - mu;
  float var = block_sum(d*d, red) * (1.f/Hsz);
  d_attn0[b*Hsz + j] = d * rsqrtf(var + 1e-12f) * g1[j] + be1[j];
}

// ============ FFN1 partials (f32x2 over b-pairs) ============
__global__ void k_ffn1(const float* __restrict__ w1){
  int mc = blockIdx.x, is = blockIdx.y;             // 24 x 8
  int t = threadIdx.x;                              // 128
  int m = mc*128 + t, i0 = is*96;
  __shared__ ull as2[8*96];
  #pragma unroll
  for (int k = 0; k < 6; k++){
    int n = t + 128*k;
    int bp = n / 96, i = n % 96;
    as2[n] = pk2(d_attn0[(2*bp)*Hsz + i0 + i], d_attn0[(2*bp+1)*Hsz + i0 + i]);
  }
  __syncthreads();
  ull acc2[8];
  #pragma unroll
  for (int k = 0; k < 8; k++) acc2[k] = 0ull;
  #pragma unroll 2
  for (int i = 0; i < 96; i++){
    float w = w1[(size_t)(i0+i)*FFs + m];
    ull w2 = pk2(w, w);
    #pragma unroll
    for (int bp = 0; bp < 8; bp++)
      acc2[bp] = ffma2(as2[bp*96 + i], w2, acc2[bp]);
  }
  #pragma unroll
  for (int bp = 0; bp < 8; bp++){
    float lo, hi; upk2(lo, hi, acc2[bp]);
    d_gpart[(size_t)(is*Bsz + 2*bp)*FFs + m]   = lo;
    d_gpart[(size_t)(is*Bsz + 2*bp+1)*FFs + m] = hi;
  }
}

// ============ reduce + bias + exact GELU ============
__global__ void k_gelu(const float* __restrict__ b1){
  int n = blockIdx.x*256 + threadIdx.x;             // < 49152
  float s = b1[n % FFs];
  #pragma unroll
  for (int is = 0; is < 8; is++) s += d_gpart[(size_t)is*(Bsz*FFs) + n];
  d_g[n] = 0.5f * s * (1.f + erff(s * 0.70710678118654752f));
}

// ============ FFN2 partials (f32x2 over b-pairs, K-split 24) ============
__global__ void k_ffn2(const float* __restrict__ w2){
  int jc = blockIdx.x, ms = blockIdx.y;             // 6 x 24
  int t = threadIdx.x;                              // 128
  int j = jc*128 + t, m0 = ms*128;
  __shared__ ull gs2[8*128];
  #pragma unroll
  for (int k = 0; k < 8; k++){
    int n = t + 128*k;
    int bp = n >> 7, mm = n & 127;
    gs2[n] = pk2(d_g[(2*bp)*FFs + m0 + mm], d_g[(2*bp+1)*FFs + m0 + mm]);
  }
  __syncthreads();
  ull acc2[8];
  #pragma unroll
  for (int k = 0; k < 8; k++) acc2[k] = 0ull;
  #pragma unroll 2
  for (int mm = 0; mm < 128; mm++){
    float w = w2[(size_t)(m0+mm)*Hsz + j];
    ull wpk = pk2(w, w);
    #pragma unroll
    for (int bp = 0; bp < 8; bp++)
      acc2[bp] = ffma2(gs2[bp*128 + mm], wpk, acc2[bp]);
  }
  #pragma unroll
  for (int bp = 0; bp < 8; bp++){
    float lo, hi; upk2(lo, hi, acc2[bp]);
    d_opart[(size_t)(ms*Bsz + 2*bp)*Hsz + j]   = lo;
    d_opart[(size_t)(ms*Bsz + 2*bp+1)*Hsz + j] = hi;
  }
}

// ============ LN2: hid = LN(ffn + b2 + attn0) ============
__global__ void k_ln2(const float* __restrict__ b2, const float* __restrict__ g2,
                      const float* __restrict__ be2){
  int b = blockIdx.x, j = threadIdx.x;              // 16 x 768
  __shared__ float red[32];
  float y = b2[j] + d_attn0[b*Hsz + j];
  #pragma unroll
  for (int ms = 0; ms < 24; ms++) y += d_opart[(size_t)(ms*Bsz + b)*Hsz + j];
  float mu  = block_sum(y, red) * (1.f/Hsz);
  float d   = y - mu;
  float var = block_sum(d*d, red) * (1.f/Hsz);
  d_hid[b*Hsz + j] = d * rsqrtf(var + 1e-12f) * g2[j] + be2[j];
}

// ============ pool partials: hid @ wp + bp (K-split 12) ============
__global__ void k_poolp(const float* __restrict__ wp, const float* __restrict__ bp){
  int jc = blockIdx.x, ks = blockIdx.y;             // 6 x 12
  int t = threadIdx.x;                              // 256
  int j0 = jc*128, i0 = ks*64;
  __shared__ float Hs[Bsz*64];
  #pragma unroll
  for (int k = 0; k < 4; k++){
    int v = t + 256*k;
    Hs[v] = d_hid[(v>>6)*Hsz + i0 + (v&63)];
  }
  __syncthreads();
  int j = j0 + (t & 127), bh = t >> 7;
  float binit = (ks == 0) ? bp[j] : 0.f;
  float acc[8];
  #pragma unroll
  for (int bb = 0; bb < 8; bb++) acc[bb] = binit;
  #pragma unroll 4
  for (int i = 0; i < 64; i++){
    float w = wp[(size_t)(i0+i)*Hsz + j];
    #pragma unroll
    for (int bb = 0; bb < 8; bb++)
      acc[bb] = fmaf(Hs[(bh*8+bb)*64 + i], w, acc[bb]);
  }
  #pragma unroll
  for (int bb = 0; bb < 8; bb++)
    d_pp[ks*(Bsz*Hsz) + (bh*8+bb)*Hsz + j] = acc[bb];
}

// ============ final: pooled = tanh(.), cls = pooled @ wm + bm ============
__global__ void k_cls(const float* __restrict__ wm, const float* __restrict__ bm,
                      float* __restrict__ out){
  int b = blockIdx.x, j = threadIdx.x;              // 16 x 768
  __shared__ float red[32];
  float y = 0.f;
  #pragma unroll
  for (int ks = 0; ks < 12; ks++) y += d_pp[ks*(Bsz*Hsz) + b*Hsz + j];
  float pj = tanhf(y);
  float c = block_sum(pj * wm[j], red);
  if (j == 0) out[b] = c + bm[0];
}

// ---------------- launch ----------------
extern "C" void kernel_launch(void* const* d_in, const int* in_sizes, int n_in,
                              void* d_out, int out_size){
  (void)in_sizes; (void)n_in; (void)out_size;
  const float* features = (const float*)d_in[0];
  const float* mask     = (const float*)d_in[1];
  const float* wq  = (const float*)d_in[2];
  const float* bq  = (const float*)d_in[3];
  const float* wk  = (const float*)d_in[4];
  const float* bk  = (const float*)d_in[5];
  const float* wv  = (const float*)d_in[6];
  const float* bv  = (const float*)d_in[7];
  const float* wo  = (const float*)d_in[8];
  const float* bo  = (const float*)d_in[9];
  const float* ln1g = (const float*)d_in[10];
  const float* ln1b = (const float*)d_in[11];
  const float* w1  = (const float*)d_in[12];
  const float* b1  = (const float*)d_in[13];
  const float* w2  = (const float*)d_in[14];
  const float* b2  = (const float*)d_in[15];
  const float* ln2g = (const float*)d_in[16];
  const float* ln2b = (const float*)d_in[17];
  const float* wp  = (const float*)d_in[18];
  const float* bp  = (const float*)d_in[19];
  const float* wm  = (const float*)d_in[20];
  const float* bm  = (const float*)d_in[21];
  float* out = (float*)d_out;

  k_q0p   <<<dim3(6,12), 256>>>(features, wq, bq);
  k_u     <<<dim3(12,6), 256>>>(wk, bk);
  k_scores<<<dim3(16,16),256>>>(features, mask);
  k_softmax<<<Bsz*NHs, 1024>>>();
  k_fbar  <<<dim3(16,16),192>>>(features);
  k_ctxp  <<<dim3(6,12), 256>>>(wv);
  k_yp    <<<dim3(6,12), 256>>>(wo, bv);
  k_ln1   <<<Bsz, Hsz>>>(features, bo, ln1g, ln1b);
  k_ffn1  <<<dim3(24,8), 128>>>(w1);
  k_gelu  <<<192, 256>>>(b1);
  k_ffn2  <<<dim3(6,24), 128>>>(w2);
  k_ln2   <<<Bsz, Hsz>>>(b2, ln2g, ln2b);
  k_poolp <<<dim3(6,12), 256>>>(wp, bp);
  k_cls   <<<Bsz, Hsz>>>(wm, bm, out);
}

// round 3
// speedup vs baseline: 2.4559x; 1.0620x over previous
#include <cuda_runtime.h>
#include <math.h>

#define Bsz 16
#define Ssz 1024
#define Hsz 768
#define NHs 12
#define Dh  64
#define FFs 3072
#define NB  256
#define NT  256

// ---------------- scratch (device globals; no allocation) ----------------
__device__ float d_q0p[12*Bsz*Hsz];
__device__ float d_u[Bsz*NHs*Hsz];            // prescaled by 1/8
__device__ float d_qbk[Bsz*NHs];
__device__ float d_scores[Bsz*NHs*Ssz];       // scores -> probs in place
__device__ float d_fbp[16*Bsz*NHs*Hsz];       // fbar partials over 16 s-chunks
__device__ float d_ctxp[12*Bsz*Hsz];
__device__ float d_yp[12*Bsz*Hsz];
__device__ float d_attn0[Bsz*Hsz];
__device__ float d_gpart[8*Bsz*FFs];
__device__ float d_g[Bsz*FFs];
__device__ float d_opart[24*Bsz*Hsz];
__device__ float d_hid[Bsz*Hsz];
__device__ float d_pp[12*Bsz*Hsz];

__device__ unsigned d_bar_count = 0;
__device__ unsigned d_bar_gen = 0;

typedef unsigned long long ull;

// ---------------- f32x2 packed math ----------------
__device__ __forceinline__ ull ffma2(ull a, ull b, ull c){
  ull d; asm("fma.rn.f32x2 %0, %1, %2, %3;" : "=l"(d) : "l"(a), "l"(b), "l"(c)); return d;
}
__device__ __forceinline__ ull pk2(float lo, float hi){
  ull r; asm("mov.b64 %0, {%1, %2};" : "=l"(r) : "f"(lo), "f"(hi)); return r;
}
__device__ __forceinline__ void upk2(float& lo, float& hi, ull v){
  asm("mov.b64 {%0, %1}, %2;" : "=f"(lo), "=f"(hi) : "l"(v));
}

// ---------------- block reductions ----------------
__device__ __forceinline__ float block_sum(float v, float* red){
  int lane = threadIdx.x & 31, w = threadIdx.x >> 5;
  #pragma unroll
  for (int o = 16; o; o >>= 1) v += __shfl_xor_sync(0xffffffffu, v, o);
  if (lane == 0) red[w] = v;
  __syncthreads();
  float s = (lane < (NT>>5)) ? red[lane] : 0.f;
  #pragma unroll
  for (int o = 16; o; o >>= 1) s += __shfl_xor_sync(0xffffffffu, s, o);
  __syncthreads();
  return s;
}
__device__ __forceinline__ float block_max(float v, float* red){
  int lane = threadIdx.x & 31, w = threadIdx.x >> 5;
  #pragma unroll
  for (int o = 16; o; o >>= 1) v = fmaxf(v, __shfl_xor_sync(0xffffffffu, v, o));
  if (lane == 0) red[w] = v;
  __syncthreads();
  float s = (lane < (NT>>5)) ? red[lane] : -INFINITY;
  #pragma unroll
  for (int o = 16; o; o >>= 1) s = fmaxf(s, __shfl_xor_sync(0xffffffffu, s, o));
  __syncthreads();
  return s;
}

// ---------------- grid-wide barrier (all 256 blocks resident) ----------------
__device__ __forceinline__ void gsync(){
  __syncthreads();
  if (threadIdx.x == 0){
    __threadfence();                             // release: my stores -> L2
    unsigned gen = atomicAdd(&d_bar_gen, 0u);    // read gen BEFORE arriving
    unsigned arr = atomicAdd(&d_bar_count, 1u);
    if (arr == NB - 1u){
      d_bar_count = 0u;
      __threadfence();
      atomicExch(&d_bar_gen, gen + 1u);
    } else {
      while (atomicAdd(&d_bar_gen, 0u) == gen) __nanosleep(64);
    }
  }
  __syncthreads();
  __threadfence();   // acquire + L1D invalidate (CCTL.IVALL on sm_103a)
}

// =========================== the whole model ===========================
__global__ void __launch_bounds__(NT, 2)
bert_head(const float* __restrict__ f,  const float* __restrict__ mask,
          const float* __restrict__ wq, const float* __restrict__ bq,
          const float* __restrict__ wk, const float* __restrict__ bk,
          const float* __restrict__ wv, const float* __restrict__ bv,
          const float* __restrict__ wo, const float* __restrict__ bo,
          const float* __restrict__ g1, const float* __restrict__ be1,
          const float* __restrict__ w1, const float* __restrict__ b1,
          const float* __restrict__ w2, const float* __restrict__ b2,
          const float* __restrict__ g2, const float* __restrict__ be2,
          const float* __restrict__ wp, const float* __restrict__ bp,
          const float* __restrict__ wm, const float* __restrict__ bm,
          float* __restrict__ out){
  __shared__ __align__(16) ull sbuf[1024];       // 8KB shared scratch (union)
  __shared__ float sred[32];
  float* sf = reinterpret_cast<float*>(sbuf);
  const int t = threadIdx.x, bid = blockIdx.x;

  // ---- P1: q0 partials: q0[b,j] = f0[b,:]@wq + bq, K-split 12 (W=72) ----
  if (bid < 72){
    int jc = bid % 6, ks = bid / 6;
    int j0 = jc*128, i0 = ks*64;
    #pragma unroll
    for (int k = 0; k < 4; k++){
      int v = t + 256*k;
      sf[v] = f[(size_t)(v>>6)*Ssz*Hsz + i0 + (v&63)];
    }
    __syncthreads();
    int j = j0 + (t & 127), bh = t >> 7;
    float binit = (ks == 0) ? bq[j] : 0.f;
    float acc[8];
    #pragma unroll
    for (int bb = 0; bb < 8; bb++) acc[bb] = binit;
    #pragma unroll 4
    for (int i = 0; i < 64; i++){
      float w = wq[(size_t)(i0+i)*Hsz + j];
      #pragma unroll
      for (int bb = 0; bb < 8; bb++)
        acc[bb] = fmaf(sf[(bh*8+bb)*64 + i], w, acc[bb]);
    }
    #pragma unroll
    for (int bb = 0; bb < 8; bb++)
      d_q0p[ks*(Bsz*Hsz) + (bh*8+bb)*Hsz + j] = acc[bb];
  }
  gsync();

  // ---- P2: u[b,h,i] = Wk_h q0[b,h] / 8 ; qbk (W=72) ----
  if (bid < 72){
    int h = bid % 12, ic = bid / 12;
    #pragma unroll
    for (int k = 0; k < 4; k++){
      int v = t + 256*k;                         // b*64+d
      float s = 0.f;
      #pragma unroll
      for (int p = 0; p < 12; p++)
        s += d_q0p[p*(Bsz*Hsz) + (v>>6)*Hsz + h*Dh + (v&63)];
      sf[v] = s;
    }
    __syncthreads();
    if (ic == 0 && t < Bsz){
      float s = 0.f;
      for (int d = 0; d < Dh; d++) s += sf[t*Dh + d]*bk[h*Dh + d];
      d_qbk[t*NHs + h] = s * 0.125f;
    }
    int i = ic*128 + (t & 127), bh = t >> 7;
    const float4* wr = reinterpret_cast<const float4*>(wk + (size_t)i*Hsz + h*Dh);
    float acc[8] = {0,0,0,0,0,0,0,0};
    #pragma unroll
    for (int d4 = 0; d4 < Dh/4; d4++){
      float4 w = wr[d4];
      #pragma unroll
      for (int bb = 0; bb < 8; bb++){
        float4 q = *reinterpret_cast<const float4*>(&sf[(bh*8+bb)*Dh + d4*4]);
        acc[bb] = fmaf(w.x,q.x, fmaf(w.y,q.y, fmaf(w.z,q.z, fmaf(w.w,q.w, acc[bb]))));
      }
    }
    #pragma unroll
    for (int bb = 0; bb < 8; bb++)
      d_u[((bh*8+bb)*NHs + h)*Hsz + i] = acc[bb] * 0.125f;
  }
  gsync();

  // ---- P3: scores[b,h,s] = f[b,s,:].u[b,h,:] + qbk + mask (W=256) ----
  {
    int sc = bid % 16, b = bid / 16;
    int r = t >> 2, q = t & 3;
    ull acc2[NHs];
    #pragma unroll
    for (int h = 0; h < NHs; h++) acc2[h] = 0ull;
    const float* fbase = f + ((size_t)b*Ssz + sc*64)*Hsz;
    const float* ubase = d_u + (size_t)b*NHs*Hsz;
    for (int ic = 0; ic < Hsz/32; ic++){
      __syncthreads();
      sf[t] = ubase[(t>>5)*Hsz + ic*32 + (t&31)];
      if (t < 128){ int n = t + 256; sf[n] = ubase[(n>>5)*Hsz + ic*32 + (n&31)]; }
      __syncthreads();
      #pragma unroll
      for (int g = 0; g < 2; g++){
        ulonglong2 fv = *reinterpret_cast<const ulonglong2*>(
            fbase + (size_t)r*Hsz + ic*32 + q*8 + g*4);
        #pragma unroll
        for (int h = 0; h < NHs; h++){
          ulonglong2 uv = *reinterpret_cast<const ulonglong2*>(&sf[h*32 + q*8 + g*4]);
          acc2[h] = ffma2(fv.x, uv.x, acc2[h]);
          acc2[h] = ffma2(fv.y, uv.y, acc2[h]);
        }
      }
    }
    int srow = sc*64 + r;
    float m = mask[b*Ssz + srow];
    #pragma unroll
    for (int h = 0; h < NHs; h++){
      float lo, hi; upk2(lo, hi, acc2[h]);
      float v = lo + hi;
      v += __shfl_xor_sync(0xffffffffu, v, 1);
      v += __shfl_xor_sync(0xffffffffu, v, 2);
      if (q == 0)
        d_scores[(size_t)(b*NHs + h)*Ssz + srow] = v + d_qbk[b*NHs + h] + m;
    }
  }
  gsync();

  // ---- P4: softmax per (b,h) row in place (W=192) ----
  if (bid < 192){
    float* p = d_scores + (size_t)bid * Ssz;
    float v0 = p[t], v1 = p[t+256], v2 = p[t+512], v3 = p[t+768];
    float m = block_max(fmaxf(fmaxf(v0,v1), fmaxf(v2,v3)), sred);
    v0 = expf(v0-m); v1 = expf(v1-m); v2 = expf(v2-m); v3 = expf(v3-m);
    float s = block_sum(v0+v1+v2+v3, sred);
    float inv = 1.f / s;
    p[t] = v0*inv; p[t+256] = v1*inv; p[t+512] = v2*inv; p[t+768] = v3*inv;
  }
  gsync();

  // ---- P5: fbar partials over 16 s-chunks (W=256) ----
  {
    int b = bid % 16, sc = bid / 16;
    for (int n = t; n < NHs*64; n += 256){
      float pv = d_scores[(size_t)(b*NHs + (n>>6))*Ssz + sc*64 + (n&63)];
      sbuf[n] = pk2(pv, pv);
    }
    __syncthreads();
    if (t < 192){
      ull acc2[2*NHs];
      #pragma unroll
      for (int k = 0; k < 2*NHs; k++) acc2[k] = 0ull;
      const float* fb = f + ((size_t)b*Ssz + sc*64)*Hsz + t*4;
      for (int s = 0; s < 64; s++){
        ulonglong2 fv = *reinterpret_cast<const ulonglong2*>(fb + (size_t)s*Hsz);
        #pragma unroll
        for (int h = 0; h < NHs; h++){
          ull pp = sbuf[h*64 + s];
          acc2[2*h]   = ffma2(pp, fv.x, acc2[2*h]);
          acc2[2*h+1] = ffma2(pp, fv.y, acc2[2*h+1]);
        }
      }
      #pragma unroll
      for (int h = 0; h < NHs; h++){
        float4 o;
        upk2(o.x, o.y, acc2[2*h]);
        upk2(o.z, o.w, acc2[2*h+1]);
        *reinterpret_cast<float4*>(
          &d_fbp[((size_t)(sc*Bsz + b)*NHs + h)*Hsz + t*4]) = o;
      }
    }
  }
  gsync();

  // ---- P6: ctx partials: fbar[b,h(j),:] @ wv[:,j], K-split 12 (W=72) ----
  if (bid < 72){
    int jc = bid % 6, ks = bid / 6;
    int j0 = jc*128, i0 = ks*64, h0 = jc*2;
    #pragma unroll
    for (int k = 0; k < 8; k++){
      int v = t + 256*k;
      int bb = v>>7, hl = (v>>6)&1, i = v&63;
      float s = 0.f;
      #pragma unroll
      for (int sc = 0; sc < 16; sc++)
        s += d_fbp[((size_t)(sc*Bsz + bb)*NHs + h0 + hl)*Hsz + i0 + i];
      sf[v] = s;
    }
    __syncthreads();
    int j = j0 + (t & 127), hl = (t & 127) >> 6, bh = t >> 7;
    float acc[8] = {0,0,0,0,0,0,0,0};
    #pragma unroll 4
    for (int i = 0; i < 64; i++){
      float w = wv[(size_t)(i0+i)*Hsz + j];
      #pragma unroll
      for (int bb = 0; bb < 8; bb++)
        acc[bb] = fmaf(sf[(bh*8+bb)*128 + hl*64 + i], w, acc[bb]);
    }
    #pragma unroll
    for (int bb = 0; bb < 8; bb++)
      d_ctxp[ks*(Bsz*Hsz) + (bh*8+bb)*Hsz + j] = acc[bb];
  }
  gsync();

  // ---- P7: y partials: (ctx+bv) @ wo[:,j], K-split 12 (W=72) ----
  if (bid < 72){
    int jc = bid % 6, ks = bid / 6;
    int j0 = jc*128, i0 = ks*64;
    #pragma unroll
    for (int k = 0; k < 4; k++){
      int v = t + 256*k;
      int bb = v>>6, i = v&63;
      float s = bv[i0 + i];
      #pragma unroll
      for (int p = 0; p < 12; p++)
        s += d_ctxp[p*(Bsz*Hsz) + bb*Hsz + i0 + i];
      sf[v] = s;
    }
    __syncthreads();
    int j = j0 + (t & 127), bh = t >> 7;
    float acc[8] = {0,0,0,0,0,0,0,0};
    #pragma unroll 4
    for (int i = 0; i < 64; i++){
      float w = wo[(size_t)(i0+i)*Hsz + j];
      #pragma unroll
      for (int bb = 0; bb < 8; bb++)
        acc[bb] = fmaf(sf[(bh*8+bb)*64 + i], w, acc[bb]);
    }
    #pragma unroll
    for (int bb = 0; bb < 8; bb++)
      d_yp[ks*(Bsz*Hsz) + (bh*8+bb)*Hsz + j] = acc[bb];
  }
  gsync();

  // ---- P8: LN1 (W=16) ----
  if (bid < 16){
    int b = bid;
    float yv[3];
    #pragma unroll
    for (int kk = 0; kk < 3; kk++){
      int j = t + 256*kk;
      float y = bo[j] + f[(size_t)b*Ssz*Hsz + j];
      #pragma unroll
      for (int ks = 0; ks < 12; ks++) y += d_yp[ks*(Bsz*Hsz) + b*Hsz + j];
      yv[kk] = y;
    }
    float mu = block_sum(yv[0]+yv[1]+yv[2], sred) * (1.f/Hsz);
    float ss = 0.f;
    #pragma unroll
    for (int kk = 0; kk < 3; kk++){ float d = yv[kk]-mu; ss += d*d; }
    float var = block_sum(ss, sred) * (1.f/Hsz);
    float inv = rsqrtf(var + 1e-12f);
    #pragma unroll
    for (int kk = 0; kk < 3; kk++){
      int j = t + 256*kk;
      d_attn0[b*Hsz + j] = (yv[kk]-mu) * inv * g1[j] + be1[j];
    }
  }
  gsync();

  // ---- P9: FFN1 partials, f32x2 b-pairs (W=96) ----
  if (bid < 96){
    int mc = bid % 12, is = bid / 12;
    int m = mc*256 + t, i0 = is*96;
    for (int n = t; n < 8*96; n += 256){
      int bp = n / 96, i = n % 96;
      sbuf[n] = pk2(d_attn0[(2*bp)*Hsz + i0 + i], d_attn0[(2*bp+1)*Hsz + i0 + i]);
    }
    __syncthreads();
    ull acc2[8];
    #pragma unroll
    for (int k = 0; k < 8; k++) acc2[k] = 0ull;
    #pragma unroll 2
    for (int i = 0; i < 96; i++){
      float w = w1[(size_t)(i0+i)*FFs + m];
      ull wpk = pk2(w, w);
      #pragma unroll
      for (int bp = 0; bp < 8; bp++)
        acc2[bp] = ffma2(sbuf[bp*96 + i], wpk, acc2[bp]);
    }
    #pragma unroll
    for (int bp = 0; bp < 8; bp++){
      float lo, hi; upk2(lo, hi, acc2[bp]);
      d_gpart[(size_t)(is*Bsz + 2*bp)*FFs + m]   = lo;
      d_gpart[(size_t)(is*Bsz + 2*bp+1)*FFs + m] = hi;
    }
  }
  gsync();

  // ---- P10: reduce + bias + exact GELU (W=192) ----
  if (bid < 192){
    int n = bid*256 + t;
    float s = b1[n % FFs];
    #pragma unroll
    for (int is = 0; is < 8; is++) s += d_gpart[(size_t)is*(Bsz*FFs) + n];
    d_g[n] = 0.5f * s * (1.f + erff(s * 0.70710678118654752f));
  }
  gsync();

  // ---- P11: FFN2 partials, f32x2 b-pairs, K-split 24 (W=72) ----
  if (bid < 72){
    int jc = bid % 3, ms = bid / 3;
    int j = jc*256 + t, m0 = ms*128;
    #pragma unroll
    for (int k = 0; k < 4; k++){
      int n = t + 256*k;
      int bp = n >> 7, mm = n & 127;
      sbuf[n] = pk2(d_g[(2*bp)*FFs + m0 + mm], d_g[(2*bp+1)*FFs + m0 + mm]);
    }
    __syncthreads();
    ull acc2[8];
    #pragma unroll
    for (int k = 0; k < 8; k++) acc2[k] = 0ull;
    #pragma unroll 2
    for (int mm = 0; mm < 128; mm++){
      float w = w2[(size_t)(m0+mm)*Hsz + j];
      ull wpk = pk2(w, w);
      #pragma unroll
      for (int bp = 0; bp < 8; bp++)
        acc2[bp] = ffma2(sbuf[bp*128 + mm], wpk, acc2[bp]);
    }
    #pragma unroll
    for (int bp = 0; bp < 8; bp++){
      float lo, hi; upk2(lo, hi, acc2[bp]);
      d_opart[(size_t)(ms*Bsz + 2*bp)*Hsz + j]   = lo;
      d_opart[(size_t)(ms*Bsz + 2*bp+1)*Hsz + j] = hi;
    }
  }
  gsync();

  // ---- P12: LN2 (W=16) ----
  if (bid < 16){
    int b = bid;
    float yv[3];
    #pragma unroll
    for (int kk = 0; kk < 3; kk++){
      int j = t + 256*kk;
      float y = b2[j] + d_attn0[b*Hsz + j];
      #pragma unroll
      for (int ms = 0; ms < 24; ms++) y += d_opart[(size_t)(ms*Bsz + b)*Hsz + j];
      yv[kk] = y;
    }
    float mu = block_sum(yv[0]+yv[1]+yv[2], sred) * (1.f/Hsz);
    float ss = 0.f;
    #pragma unroll
    for (int kk = 0; kk < 3; kk++){ float d = yv[kk]-mu; ss += d*d; }
    float var = block_sum(ss, sred) * (1.f/Hsz);
    float inv = rsqrtf(var + 1e-12f);
    #pragma unroll
    for (int kk = 0; kk < 3; kk++){
      int j = t + 256*kk;
      d_hid[b*Hsz + j] = (yv[kk]-mu) * inv * g2[j] + be2[j];
    }
  }
  gsync();

  // ---- P13: pool partials: hid @ wp + bp, K-split 12 (W=72) ----
  if (bid < 72){
    int jc = bid % 6, ks = bid / 6;
    int j0 = jc*128, i0 = ks*64;
    #pragma unroll
    for (int k = 0; k < 4; k++){
      int v = t + 256*k;
      sf[v] = d_hid[(v>>6)*Hsz + i0 + (v&63)];
    }
    __syncthreads();
    int j = j0 + (t & 127), bh = t >> 7;
    float binit = (ks == 0) ? bp[j] : 0.f;
    float acc[8];
    #pragma unroll
    for (int bb = 0; bb < 8; bb++) acc[bb] = binit;
    #pragma unroll 4
    for (int i = 0; i < 64; i++){
      float w = wp[(size_t)(i0+i)*Hsz + j];
      #pragma unroll
      for (int bb = 0; bb < 8; bb++)
        acc[bb] = fmaf(sf[(bh*8+bb)*64 + i], w, acc[bb]);
    }
    #pragma unroll
    for (int bb = 0; bb < 8; bb++)
      d_pp[ks*(Bsz*Hsz) + (bh*8+bb)*Hsz + j] = acc[bb];
  }
  gsync();

  // ---- P14: pooled = tanh(.), cls = pooled @ wm + bm (W=16) ----
  if (bid < 16){
    int b = bid;
    float contrib = 0.f;
    #pragma unroll
    for (int kk = 0; kk < 3; kk++){
      int j = t + 256*kk;
      float y = 0.f;
      #pragma unroll
      for (int ks = 0; ks < 12; ks++) y += d_pp[ks*(Bsz*Hsz) + b*Hsz + j];
      contrib += tanhf(y) * wm[j];
    }
    float c = block_sum(contrib, sred);
    if (t == 0) out[b] = c + bm[0];
  }
}

// ---------------- launch ----------------
extern "C" void kernel_launch(void* const* d_in, const int* in_sizes, int n_in,
                              void* d_out, int out_size){
  (void)in_sizes; (void)n_in; (void)out_size;
  bert_head<<<NB, NT>>>(
    (const float*)d_in[0],  (const float*)d_in[1],
    (const float*)d_in[2],  (const float*)d_in[3],
    (const float*)d_in[4],  (const float*)d_in[5],
    (const float*)d_in[6],  (const float*)d_in[7],
    (const float*)d_in[8],  (const float*)d_in[9],
    (const float*)d_in[10], (const float*)d_in[11],
    (const float*)d_in[12], (const float*)d_in[13],
    (const float*)d_in[14], (const float*)d_in[15],
    (const float*)d_in[16], (const float*)d_in[17],
    (const float*)d_in[18], (const float*)d_in[19],
    (const float*)d_in[20], (const float*)d_in[21],
    (float*)d_out);
}

// round 4
// speedup vs baseline: 2.8225x; 1.1492x over previous
#include <cuda_runtime.h>
#include <math.h>

#define Bsz 16
#define Ssz 1024
#define Hsz 768
#define NHs 12
#define Dh  64
#define FFs 3072
#define NB  256
#define NT  256

// ---------------- scratch (device globals; no allocation) ----------------
__device__ float d_q0p[12*Bsz*Hsz];
__device__ float d_u[Bsz*NHs*Hsz];            // prescaled by 1/8
__device__ float d_qbk[Bsz*NHs];
__device__ float d_scores[Bsz*NHs*Ssz];       // scores -> probs in place
__device__ float d_fbp[16*Bsz*NHs*Hsz];       // fbar partials over 16 s-chunks
__device__ float d_ctxp[12*Bsz*Hsz];
__device__ float d_yp[12*Bsz*Hsz];
__device__ float d_attn0[Bsz*Hsz];
__device__ float d_gpart[8*Bsz*FFs];
__device__ float d_g[Bsz*FFs];
__device__ float d_opart[24*Bsz*Hsz];
__device__ float d_hid[Bsz*Hsz];
__device__ float d_pp[12*Bsz*Hsz];

__device__ unsigned d_bar_count = 0;
__device__ unsigned d_bar_gen = 0;

typedef unsigned long long ull;

// ---------------- f32x2 packed math ----------------
__device__ __forceinline__ ull ffma2(ull a, ull b, ull c){
  ull d; asm("fma.rn.f32x2 %0, %1, %2, %3;" : "=l"(d) : "l"(a), "l"(b), "l"(c)); return d;
}
__device__ __forceinline__ ull pk2(float lo, float hi){
  ull r; asm("mov.b64 %0, {%1, %2};" : "=l"(r) : "f"(lo), "f"(hi)); return r;
}
__device__ __forceinline__ void upk2(float& lo, float& hi, ull v){
  asm("mov.b64 {%0, %1}, %2;" : "=f"(lo), "=f"(hi) : "l"(v));
}

// ---------------- block reductions ----------------
__device__ __forceinline__ float block_sum(float v, float* red){
  int lane = threadIdx.x & 31, w = threadIdx.x >> 5;
  #pragma unroll
  for (int o = 16; o; o >>= 1) v += __shfl_xor_sync(0xffffffffu, v, o);
  if (lane == 0) red[w] = v;
  __syncthreads();
  float s = (lane < (NT>>5)) ? red[lane] : 0.f;
  #pragma unroll
  for (int o = 16; o; o >>= 1) s += __shfl_xor_sync(0xffffffffu, s, o);
  __syncthreads();
  return s;
}
__device__ __forceinline__ float block_max(float v, float* red){
  int lane = threadIdx.x & 31, w = threadIdx.x >> 5;
  #pragma unroll
  for (int o = 16; o; o >>= 1) v = fmaxf(v, __shfl_xor_sync(0xffffffffu, v, o));
  if (lane == 0) red[w] = v;
  __syncthreads();
  float s = (lane < (NT>>5)) ? red[lane] : -INFINITY;
  #pragma unroll
  for (int o = 16; o; o >>= 1) s = fmaxf(s, __shfl_xor_sync(0xffffffffu, s, o));
  __syncthreads();
  return s;
}

// ------- grid barrier: arrive = 1 atomic/block, poll = plain acquire LOADS -------
__device__ __forceinline__ void gsync(){
  __syncthreads();
  if (threadIdx.x == 0){
    unsigned gen;
    asm volatile("ld.volatile.global.u32 %0, [%1];"
                 : "=r"(gen) : "l"(&d_bar_gen) : "memory");
    unsigned arr;
    asm volatile("atom.add.release.gpu.global.u32 %0, [%1], 1;"
                 : "=r"(arr) : "l"(&d_bar_count) : "memory");
    if (arr == NB - 1u){
      asm volatile("st.global.u32 [%0], %1;" :: "l"(&d_bar_count), "r"(0u) : "memory");
      asm volatile("st.release.gpu.global.u32 [%0], %1;"
                   :: "l"(&d_bar_gen), "r"(gen + 1u) : "memory");
    } else {
      unsigned g;
      do {
        __nanosleep(64);
        asm volatile("ld.acquire.gpu.global.u32 %0, [%1];"
                     : "=r"(g) : "l"(&d_bar_gen) : "memory");
      } while (g == gen);
    }
    __threadfence();   // CCTL.IVALL: invalidate this SM's L1 for post-barrier loads
  }
  __syncthreads();
}

// =========================== the whole model ===========================
__global__ void __launch_bounds__(NT, 2)
bert_head(const float* __restrict__ f,  const float* __restrict__ mask,
          const float* __restrict__ wq, const float* __restrict__ bq,
          const float* __restrict__ wk, const float* __restrict__ bk,
          const float* __restrict__ wv, const float* __restrict__ bv,
          const float* __restrict__ wo, const float* __restrict__ bo,
          const float* __restrict__ g1, const float* __restrict__ be1,
          const float* __restrict__ w1, const float* __restrict__ b1,
          const float* __restrict__ w2, const float* __restrict__ b2,
          const float* __restrict__ g2, const float* __restrict__ be2,
          const float* __restrict__ wp, const float* __restrict__ bp,
          const float* __restrict__ wm, const float* __restrict__ bm,
          float* __restrict__ out){
  __shared__ __align__(16) ull sbuf[1024];       // 8KB shared scratch (union)
  __shared__ float sred[32];
  float* sf = reinterpret_cast<float*>(sbuf);
  const int t = threadIdx.x, bid = blockIdx.x;

  // ---- P1: q0 partials: q0[b,j] = f0[b,:]@wq + bq, K-split 12 (W=72) ----
  if (bid < 72){
    int jc = bid % 6, ks = bid / 6;
    int j0 = jc*128, i0 = ks*64;
    #pragma unroll
    for (int k = 0; k < 4; k++){
      int v = t + 256*k;
      sf[v] = f[(size_t)(v>>6)*Ssz*Hsz + i0 + (v&63)];
    }
    __syncthreads();
    int j = j0 + (t & 127), bh = t >> 7;
    float binit = (ks == 0) ? bq[j] : 0.f;
    float acc[8];
    #pragma unroll
    for (int bb = 0; bb < 8; bb++) acc[bb] = binit;
    #pragma unroll 4
    for (int i = 0; i < 64; i++){
      float w = wq[(size_t)(i0+i)*Hsz + j];
      #pragma unroll
      for (int bb = 0; bb < 8; bb++)
        acc[bb] = fmaf(sf[(bh*8+bb)*64 + i], w, acc[bb]);
    }
    #pragma unroll
    for (int bb = 0; bb < 8; bb++)
      d_q0p[ks*(Bsz*Hsz) + (bh*8+bb)*Hsz + j] = acc[bb];
  }
  gsync();

  // ---- P2: u[b,h,i] = Wk_h q0[b,h] / 8 ; qbk (W=72) ----
  if (bid < 72){
    int h = bid % 12, ic = bid / 12;
    #pragma unroll
    for (int k = 0; k < 4; k++){
      int v = t + 256*k;                         // b*64+d
      float s = 0.f;
      #pragma unroll
      for (int p = 0; p < 12; p++)
        s += d_q0p[p*(Bsz*Hsz) + (v>>6)*Hsz + h*Dh + (v&63)];
      sf[v] = s;
    }
    __syncthreads();
    if (ic == 0 && t < Bsz){
      float s = 0.f;
      for (int d = 0; d < Dh; d++) s += sf[t*Dh + d]*bk[h*Dh + d];
      d_qbk[t*NHs + h] = s * 0.125f;
    }
    int i = ic*128 + (t & 127), bh = t >> 7;
    const float4* wr = reinterpret_cast<const float4*>(wk + (size_t)i*Hsz + h*Dh);
    float acc[8] = {0,0,0,0,0,0,0,0};
    #pragma unroll
    for (int d4 = 0; d4 < Dh/4; d4++){
      float4 w = wr[d4];
      #pragma unroll
      for (int bb = 0; bb < 8; bb++){
        float4 q = *reinterpret_cast<const float4*>(&sf[(bh*8+bb)*Dh + d4*4]);
        acc[bb] = fmaf(w.x,q.x, fmaf(w.y,q.y, fmaf(w.z,q.z, fmaf(w.w,q.w, acc[bb]))));
      }
    }
    #pragma unroll
    for (int bb = 0; bb < 8; bb++)
      d_u[((bh*8+bb)*NHs + h)*Hsz + i] = acc[bb] * 0.125f;
  }
  gsync();

  // ---- P3: scores[b,h,s] = f[b,s,:].u[b,h,:] + qbk + mask (W=256) ----
  {
    int sc = bid % 16, b = bid / 16;
    int r = t >> 2, q = t & 3;
    ull acc2[NHs];
    #pragma unroll
    for (int h = 0; h < NHs; h++) acc2[h] = 0ull;
    const float* fbase = f + ((size_t)b*Ssz + sc*64)*Hsz;
    const float* ubase = d_u + (size_t)b*NHs*Hsz;
    for (int ic = 0; ic < Hsz/32; ic++){
      __syncthreads();
      sf[t] = ubase[(t>>5)*Hsz + ic*32 + (t&31)];
      if (t < 128){ int n = t + 256; sf[n] = ubase[(n>>5)*Hsz + ic*32 + (n&31)]; }
      __syncthreads();
      #pragma unroll
      for (int g = 0; g < 2; g++){
        ulonglong2 fv = *reinterpret_cast<const ulonglong2*>(
            fbase + (size_t)r*Hsz + ic*32 + q*8 + g*4);
        #pragma unroll
        for (int h = 0; h < NHs; h++){
          ulonglong2 uv = *reinterpret_cast<const ulonglong2*>(&sf[h*32 + q*8 + g*4]);
          acc2[h] = ffma2(fv.x, uv.x, acc2[h]);
          acc2[h] = ffma2(fv.y, uv.y, acc2[h]);
        }
      }
    }
    int srow = sc*64 + r;
    float m = mask[b*Ssz + srow];
    #pragma unroll
    for (int h = 0; h < NHs; h++){
      float lo, hi; upk2(lo, hi, acc2[h]);
      float v = lo + hi;
      v += __shfl_xor_sync(0xffffffffu, v, 1);
      v += __shfl_xor_sync(0xffffffffu, v, 2);
      if (q == 0)
        d_scores[(size_t)(b*NHs + h)*Ssz + srow] = v + d_qbk[b*NHs + h] + m;
    }
  }
  gsync();

  // ---- P4: softmax per (b,h) row in place (W=192) ----
  if (bid < 192){
    float* p = d_scores + (size_t)bid * Ssz;
    float v0 = p[t], v1 = p[t+256], v2 = p[t+512], v3 = p[t+768];
    float m = block_max(fmaxf(fmaxf(v0,v1), fmaxf(v2,v3)), sred);
    v0 = expf(v0-m); v1 = expf(v1-m); v2 = expf(v2-m); v3 = expf(v3-m);
    float s = block_sum(v0+v1+v2+v3, sred);
    float inv = 1.f / s;
    p[t] = v0*inv; p[t+256] = v1*inv; p[t+512] = v2*inv; p[t+768] = v3*inv;
  }
  gsync();

  // ---- P5: fbar partials over 16 s-chunks (W=256) ----
  {
    int b = bid % 16, sc = bid / 16;
    for (int n = t; n < NHs*64; n += 256){
      float pv = d_scores[(size_t)(b*NHs + (n>>6))*Ssz + sc*64 + (n&63)];
      sbuf[n] = pk2(pv, pv);
    }
    __syncthreads();
    if (t < 192){
      ull acc2[2*NHs];
      #pragma unroll
      for (int k = 0; k < 2*NHs; k++) acc2[k] = 0ull;
      const float* fb = f + ((size_t)b*Ssz + sc*64)*Hsz + t*4;
      #pragma unroll 4
      for (int s = 0; s < 64; s++){
        ulonglong2 fv = *reinterpret_cast<const ulonglong2*>(fb + (size_t)s*Hsz);
        #pragma unroll
        for (int h = 0; h < NHs; h++){
          ull pp = sbuf[h*64 + s];
          acc2[2*h]   = ffma2(pp, fv.x, acc2[2*h]);
          acc2[2*h+1] = ffma2(pp, fv.y, acc2[2*h+1]);
        }
      }
      #pragma unroll
      for (int h = 0; h < NHs; h++){
        float4 o;
        upk2(o.x, o.y, acc2[2*h]);
        upk2(o.z, o.w, acc2[2*h+1]);
        *reinterpret_cast<float4*>(
          &d_fbp[((size_t)(sc*Bsz + b)*NHs + h)*Hsz + t*4]) = o;
      }
    }
  }
  gsync();

  // ---- P6: ctx partials: fbar[b,h(j),:] @ wv[:,j], K-split 12 (W=72) ----
  if (bid < 72){
    int jc = bid % 6, ks = bid / 6;
    int j0 = jc*128, i0 = ks*64, h0 = jc*2;
    #pragma unroll
    for (int k = 0; k < 8; k++){
      int v = t + 256*k;
      int bb = v>>7, hl = (v>>6)&1, i = v&63;
      float s = 0.f;
      #pragma unroll
      for (int sc = 0; sc < 16; sc++)
        s += d_fbp[((size_t)(sc*Bsz + bb)*NHs + h0 + hl)*Hsz + i0 + i];
      sf[v] = s;
    }
    __syncthreads();
    int j = j0 + (t & 127), hl = (t & 127) >> 6, bh = t >> 7;
    float acc[8] = {0,0,0,0,0,0,0,0};
    #pragma unroll 4
    for (int i = 0; i < 64; i++){
      float w = wv[(size_t)(i0+i)*Hsz + j];
      #pragma unroll
      for (int bb = 0; bb < 8; bb++)
        acc[bb] = fmaf(sf[(bh*8+bb)*128 + hl*64 + i], w, acc[bb]);
    }
    #pragma unroll
    for (int bb = 0; bb < 8; bb++)
      d_ctxp[ks*(Bsz*Hsz) + (bh*8+bb)*Hsz + j] = acc[bb];
  }
  gsync();

  // ---- P7: y partials: (ctx+bv) @ wo[:,j], K-split 12 (W=72) ----
  if (bid < 72){
    int jc = bid % 6, ks = bid / 6;
    int j0 = jc*128, i0 = ks*64;
    #pragma unroll
    for (int k = 0; k < 4; k++){
      int v = t + 256*k;
      int bb = v>>6, i = v&63;
      float s = bv[i0 + i];
      #pragma unroll
      for (int p = 0; p < 12; p++)
        s += d_ctxp[p*(Bsz*Hsz) + bb*Hsz + i0 + i];
      sf[v] = s;
    }
    __syncthreads();
    int j = j0 + (t & 127), bh = t >> 7;
    float acc[8] = {0,0,0,0,0,0,0,0};
    #pragma unroll 4
    for (int i = 0; i < 64; i++){
      float w = wo[(size_t)(i0+i)*Hsz + j];
      #pragma unroll
      for (int bb = 0; bb < 8; bb++)
        acc[bb] = fmaf(sf[(bh*8+bb)*64 + i], w, acc[bb]);
    }
    #pragma unroll
    for (int bb = 0; bb < 8; bb++)
      d_yp[ks*(Bsz*Hsz) + (bh*8+bb)*Hsz + j] = acc[bb];
  }
  gsync();

  // ---- P8: LN1 (W=16) ----
  if (bid < 16){
    int b = bid;
    float yv[3];
    #pragma unroll
    for (int kk = 0; kk < 3; kk++){
      int j = t + 256*kk;
      float y = bo[j] + f[(size_t)b*Ssz*Hsz + j];
      #pragma unroll
      for (int ks = 0; ks < 12; ks++) y += d_yp[ks*(Bsz*Hsz) + b*Hsz + j];
      yv[kk] = y;
    }
    float mu = block_sum(yv[0]+yv[1]+yv[2], sred) * (1.f/Hsz);
    float ss = 0.f;
    #pragma unroll
    for (int kk = 0; kk < 3; kk++){ float d = yv[kk]-mu; ss += d*d; }
    float var = block_sum(ss, sred) * (1.f/Hsz);
    float inv = rsqrtf(var + 1e-12f);
    #pragma unroll
    for (int kk = 0; kk < 3; kk++){
      int j = t + 256*kk;
      d_attn0[b*Hsz + j] = (yv[kk]-mu) * inv * g1[j] + be1[j];
    }
  }
  gsync();

  // ---- P9: FFN1 partials, f32x2 b-pairs (W=96) ----
  if (bid < 96){
    int mc = bid % 12, is = bid / 12;
    int m = mc*256 + t, i0 = is*96;
    for (int n = t; n < 8*96; n += 256){
      int bp = n / 96, i = n % 96;
      sbuf[n] = pk2(d_attn0[(2*bp)*Hsz + i0 + i], d_attn0[(2*bp+1)*Hsz + i0 + i]);
    }
    __syncthreads();
    ull acc2[8];
    #pragma unroll
    for (int k = 0; k < 8; k++) acc2[k] = 0ull;
    #pragma unroll 4
    for (int i = 0; i < 96; i++){
      float w = w1[(size_t)(i0+i)*FFs + m];
      ull wpk = pk2(w, w);
      #pragma unroll
      for (int bp = 0; bp < 8; bp++)
        acc2[bp] = ffma2(sbuf[bp*96 + i], wpk, acc2[bp]);
    }
    #pragma unroll
    for (int bp = 0; bp < 8; bp++){
      float lo, hi; upk2(lo, hi, acc2[bp]);
      d_gpart[(size_t)(is*Bsz + 2*bp)*FFs + m]   = lo;
      d_gpart[(size_t)(is*Bsz + 2*bp+1)*FFs + m] = hi;
    }
  }
  gsync();

  // ---- P10: reduce + bias + exact GELU (W=192) ----
  if (bid < 192){
    int n = bid*256 + t;
    float s = b1[n % FFs];
    #pragma unroll
    for (int is = 0; is < 8; is++) s += d_gpart[(size_t)is*(Bsz*FFs) + n];
    d_g[n] = 0.5f * s * (1.f + erff(s * 0.70710678118654752f));
  }
  gsync();

  // ---- P11: FFN2 partials, f32x2 b-pairs, K-split 24 (W=72) ----
  if (bid < 72){
    int jc = bid % 3, ms = bid / 3;
    int j = jc*256 + t, m0 = ms*128;
    #pragma unroll
    for (int k = 0; k < 4; k++){
      int n = t + 256*k;
      int bp = n >> 7, mm = n & 127;
      sbuf[n] = pk2(d_g[(2*bp)*FFs + m0 + mm], d_g[(2*bp+1)*FFs + m0 + mm]);
    }
    __syncthreads();
    ull acc2[8];
    #pragma unroll
    for (int k = 0; k < 8; k++) acc2[k] = 0ull;
    #pragma unroll 4
    for (int mm = 0; mm < 128; mm++){
      float w = w2[(size_t)(m0+mm)*Hsz + j];
      ull wpk = pk2(w, w);
      #pragma unroll
      for (int bp = 0; bp < 8; bp++)
        acc2[bp] = ffma2(sbuf[bp*128 + mm], wpk, acc2[bp]);
    }
    #pragma unroll
    for (int bp = 0; bp < 8; bp++){
      float lo, hi; upk2(lo, hi, acc2[bp]);
      d_opart[(size_t)(ms*Bsz + 2*bp)*Hsz + j]   = lo;
      d_opart[(size_t)(ms*Bsz + 2*bp+1)*Hsz + j] = hi;
    }
  }
  gsync();

  // ---- P12: LN2 (W=16) ----
  if (bid < 16){
    int b = bid;
    float yv[3];
    #pragma unroll
    for (int kk = 0; kk < 3; kk++){
      int j = t + 256*kk;
      float y = b2[j] + d_attn0[b*Hsz + j];
      #pragma unroll
      for (int ms = 0; ms < 24; ms++) y += d_opart[(size_t)(ms*Bsz + b)*Hsz + j];
      yv[kk] = y;
    }
    float mu = block_sum(yv[0]+yv[1]+yv[2], sred) * (1.f/Hsz);
    float ss = 0.f;
    #pragma unroll
    for (int kk = 0; kk < 3; kk++){ float d = yv[kk]-mu; ss += d*d; }
    float var = block_sum(ss, sred) * (1.f/Hsz);
    float inv = rsqrtf(var + 1e-12f);
    #pragma unroll
    for (int kk = 0; kk < 3; kk++){
      int j = t + 256*kk;
      d_hid[b*Hsz + j] = (yv[kk]-mu) * inv * g2[j] + be2[j];
    }
  }
  gsync();

  // ---- P13: pool partials: hid @ wp + bp, K-split 12 (W=72) ----
  if (bid < 72){
    int jc = bid % 6, ks = bid / 6;
    int j0 = jc*128, i0 = ks*64;
    #pragma unroll
    for (int k = 0; k < 4; k++){
      int v = t + 256*k;
      sf[v] = d_hid[(v>>6)*Hsz + i0 + (v&63)];
    }
    __syncthreads();
    int j = j0 + (t & 127), bh = t >> 7;
    float binit = (ks == 0) ? bp[j] : 0.f;
    float acc[8];
    #pragma unroll
    for (int bb = 0; bb < 8; bb++) acc[bb] = binit;
    #pragma unroll 4
    for (int i = 0; i < 64; i++){
      float w = wp[(size_t)(i0+i)*Hsz + j];
      #pragma unroll
      for (int bb = 0; bb < 8; bb++)
        acc[bb] = fmaf(sf[(bh*8+bb)*64 + i], w, acc[bb]);
    }
    #pragma unroll
    for (int bb = 0; bb < 8; bb++)
      d_pp[ks*(Bsz*Hsz) + (bh*8+bb)*Hsz + j] = acc[bb];
  }
  gsync();

  // ---- P14: pooled = tanh(.), cls = pooled @ wm + bm (W=16) ----
  if (bid < 16){
    int b = bid;
    float contrib = 0.f;
    #pragma unroll
    for (int kk = 0; kk < 3; kk++){
      int j = t + 256*kk;
      float y = 0.f;
      #pragma unroll
      for (int ks = 0; ks < 12; ks++) y += d_pp[ks*(Bsz*Hsz) + b*Hsz + j];
      contrib += tanhf(y) * wm[j];
    }
    float c = block_sum(contrib, sred);
    if (t == 0) out[b] = c + bm[0];
  }
}

// ---------------- launch ----------------
extern "C" void kernel_launch(void* const* d_in, const int* in_sizes, int n_in,
                              void* d_out, int out_size){
  (void)in_sizes; (void)n_in; (void)out_size;
  bert_head<<<NB, NT>>>(
    (const float*)d_in[0],  (const float*)d_in[1],
    (const float*)d_in[2],  (const float*)d_in[3],
    (const float*)d_in[4],  (const float*)d_in[5],
    (const float*)d_in[6],  (const float*)d_in[7],
    (const float*)d_in[8],  (const float*)d_in[9],
    (const float*)d_in[10], (const float*)d_in[11],
    (const float*)d_in[12], (const float*)d_in[13],
    (const float*)d_in[14], (const float*)d_in[15],
    (const float*)d_in[16], (const float*)d_in[17],
    (const float*)d_in[18], (const float*)d_in[19],
    (const float*)d_in[20], (const float*)d_in[21],
    (float*)d_out);
}

// round 5
// speedup vs baseline: 3.4948x; 1.2382x over previous
#include <cuda_runtime.h>
#include <math.h>

#define Bsz 16
#define Ssz 1024
#define Hsz 768
#define NHs 12
#define Dh  64
#define FFs 3072
#define NB  256
#define NT  256

// ---------------- scratch (device globals; no allocation) ----------------
__device__ float d_q0p[12*Bsz*Hsz];
__device__ float d_u[Bsz*NHs*Hsz];            // prescaled by 1/8
__device__ float d_qbk[Bsz*NHs];
__device__ float d_cmax[Bsz*NHs*16];          // per-chunk score max
__device__ float d_csum[Bsz*NHs*16];          // per-chunk exp-sum
__device__ float d_fbp[16*Bsz*NHs*Hsz];       // unnormalized fbar partials
__device__ float d_ctxp[12*Bsz*Hsz];
__device__ float d_yp[12*Bsz*Hsz];
__device__ float d_attn0[Bsz*Hsz];
__device__ float d_gpart[16*Bsz*FFs];
__device__ float d_g[Bsz*FFs];
__device__ float d_opart[24*Bsz*Hsz];
__device__ float d_hid[Bsz*Hsz];
__device__ float d_pp[12*Bsz*Hsz];

__device__ unsigned d_bar_count = 0;
__device__ unsigned d_bar_gen = 0;

typedef unsigned long long ull;

// ---------------- f32x2 packed math ----------------
__device__ __forceinline__ ull ffma2(ull a, ull b, ull c){
  ull d; asm("fma.rn.f32x2 %0, %1, %2, %3;" : "=l"(d) : "l"(a), "l"(b), "l"(c)); return d;
}
__device__ __forceinline__ ull pk2(float lo, float hi){
  ull r; asm("mov.b64 %0, {%1, %2};" : "=l"(r) : "f"(lo), "f"(hi)); return r;
}
__device__ __forceinline__ void upk2(float& lo, float& hi, ull v){
  asm("mov.b64 {%0, %1}, %2;" : "=f"(lo), "=f"(hi) : "l"(v));
}

// ---------------- block reductions ----------------
__device__ __forceinline__ float block_sum(float v, float* red){
  int lane = threadIdx.x & 31, w = threadIdx.x >> 5;
  #pragma unroll
  for (int o = 16; o; o >>= 1) v += __shfl_xor_sync(0xffffffffu, v, o);
  if (lane == 0) red[w] = v;
  __syncthreads();
  float s = (lane < (NT>>5)) ? red[lane] : 0.f;
  #pragma unroll
  for (int o = 16; o; o >>= 1) s += __shfl_xor_sync(0xffffffffu, s, o);
  __syncthreads();
  return s;
}

// ------- grid barrier (CG-style: leader atomics + leader fence) -------
__device__ __forceinline__ void gsync(){
  __syncthreads();
  if (threadIdx.x == 0){
    unsigned gen;
    asm volatile("ld.volatile.global.u32 %0, [%1];"
                 : "=r"(gen) : "l"(&d_bar_gen) : "memory");
    unsigned arr;
    asm volatile("atom.add.release.gpu.global.u32 %0, [%1], 1;"
                 : "=r"(arr) : "l"(&d_bar_count) : "memory");
    if (arr == NB - 1u){
      asm volatile("st.global.u32 [%0], %1;" :: "l"(&d_bar_count), "r"(0u) : "memory");
      asm volatile("st.release.gpu.global.u32 [%0], %1;"
                   :: "l"(&d_bar_gen), "r"(gen + 1u) : "memory");
    } else {
      unsigned g;
      do {
        __nanosleep(64);
        asm volatile("ld.acquire.gpu.global.u32 %0, [%1];"
                     : "=r"(g) : "l"(&d_bar_gen) : "memory");
      } while (g == gen);
    }
    __threadfence();   // CCTL.IVALL: invalidate this SM's L1 for post-barrier loads
  }
  __syncthreads();
}

// =========================== the whole model ===========================
__global__ void __launch_bounds__(NT, 2)
bert_head(const float* __restrict__ f,  const float* __restrict__ mask,
          const float* __restrict__ wq, const float* __restrict__ bq,
          const float* __restrict__ wk, const float* __restrict__ bk,
          const float* __restrict__ wv, const float* __restrict__ bv,
          const float* __restrict__ wo, const float* __restrict__ bo,
          const float* __restrict__ g1, const float* __restrict__ be1,
          const float* __restrict__ w1, const float* __restrict__ b1,
          const float* __restrict__ w2, const float* __restrict__ b2,
          const float* __restrict__ g2, const float* __restrict__ be2,
          const float* __restrict__ wp, const float* __restrict__ bp,
          const float* __restrict__ wm, const float* __restrict__ bm,
          float* __restrict__ out){
  __shared__ __align__(16) float sU[NHs*Hsz];    // 36 KB (union scratch)
  __shared__ __align__(16) float sS[64*NHs];     // 3 KB  (scores/probs etc.)
  __shared__ float sred[32];
  float* sf  = sU;
  ull*   sbuf = reinterpret_cast<ull*>(sU);
  const int t = threadIdx.x, bid = blockIdx.x;

  // ---- P1: q0 partials: q0[b,j] = f0[b,:]@wq + bq, K-split 12 (W=72) ----
  if (bid < 72){
    int jc = bid % 6, ks = bid / 6;
    int j0 = jc*128, i0 = ks*64;
    #pragma unroll
    for (int k = 0; k < 4; k++){
      int v = t + 256*k;
      sf[v] = f[(size_t)(v>>6)*Ssz*Hsz + i0 + (v&63)];
    }
    __syncthreads();
    int j = j0 + (t & 127), bh = t >> 7;
    float binit = (ks == 0) ? bq[j] : 0.f;
    float acc[8];
    #pragma unroll
    for (int bb = 0; bb < 8; bb++) acc[bb] = binit;
    #pragma unroll 4
    for (int i = 0; i < 64; i++){
      float w = wq[(size_t)(i0+i)*Hsz + j];
      #pragma unroll
      for (int bb = 0; bb < 8; bb++)
        acc[bb] = fmaf(sf[(bh*8+bb)*64 + i], w, acc[bb]);
    }
    #pragma unroll
    for (int bb = 0; bb < 8; bb++)
      d_q0p[ks*(Bsz*Hsz) + (bh*8+bb)*Hsz + j] = acc[bb];
  }
  gsync();

  // ---- P2: u[b,h,i] = Wk_h q0[b,h] / 8 ; qbk (W=72) ----
  if (bid < 72){
    int h = bid % 12, ic = bid / 12;
    #pragma unroll
    for (int k = 0; k < 4; k++){
      int v = t + 256*k;                         // b*64+d
      float s = 0.f;
      #pragma unroll
      for (int p = 0; p < 12; p++)
        s += d_q0p[p*(Bsz*Hsz) + (v>>6)*Hsz + h*Dh + (v&63)];
      sf[v] = s;
    }
    __syncthreads();
    if (ic == 0 && t < Bsz){
      float s = 0.f;
      for (int d = 0; d < Dh; d++) s += sf[t*Dh + d]*bk[h*Dh + d];
      d_qbk[t*NHs + h] = s * 0.125f;
    }
    int i = ic*128 + (t & 127), bh = t >> 7;
    const float4* wr = reinterpret_cast<const float4*>(wk + (size_t)i*Hsz + h*Dh);
    float acc[8] = {0,0,0,0,0,0,0,0};
    #pragma unroll
    for (int d4 = 0; d4 < Dh/4; d4++){
      float4 w = wr[d4];
      #pragma unroll
      for (int bb = 0; bb < 8; bb++){
        float4 q = *reinterpret_cast<const float4*>(&sf[(bh*8+bb)*Dh + d4*4]);
        acc[bb] = fmaf(w.x,q.x, fmaf(w.y,q.y, fmaf(w.z,q.z, fmaf(w.w,q.w, acc[bb]))));
      }
    }
    #pragma unroll
    for (int bb = 0; bb < 8; bb++)
      d_u[((bh*8+bb)*NHs + h)*Hsz + i] = acc[bb] * 0.125f;
  }
  gsync();

  // ---- P3': fused scores + chunk softmax + fbar partials (W=256) ----
  {
    int sc = bid & 15, b = bid >> 4;
    const float* ubase = d_u + (size_t)b*NHs*Hsz;
    const float* fbase = f + ((size_t)b*Ssz + sc*64)*Hsz;

    // stage ALL of u[b] into smem once (36 KB)
    #pragma unroll
    for (int k = 0; k < NHs*Hsz/NT; k++) sU[t + NT*k] = ubase[t + NT*k];
    __syncthreads();

    // scores: thread (r = s-row, q = i-quarter)
    {
      int r = t >> 2, q = t & 3;
      ull acc2[NHs];
      #pragma unroll
      for (int h = 0; h < NHs; h++) acc2[h] = 0ull;
      const float* frow = fbase + (size_t)r*Hsz + q*8;
      #pragma unroll 4
      for (int ic = 0; ic < 24; ic++){
        ulonglong2 fv0 = *reinterpret_cast<const ulonglong2*>(frow + ic*32);
        ulonglong2 fv1 = *reinterpret_cast<const ulonglong2*>(frow + ic*32 + 4);
        #pragma unroll
        for (int h = 0; h < NHs; h++){
          const ull* up = reinterpret_cast<const ull*>(&sU[h*Hsz + ic*32 + q*8]);
          acc2[h] = ffma2(fv0.x, up[0], acc2[h]);
          acc2[h] = ffma2(fv0.y, up[1], acc2[h]);
          acc2[h] = ffma2(fv1.x, up[2], acc2[h]);
          acc2[h] = ffma2(fv1.y, up[3], acc2[h]);
        }
      }
      int srow = sc*64 + r;
      float mv = mask[b*Ssz + srow];
      #pragma unroll
      for (int h = 0; h < NHs; h++){
        float lo, hi; upk2(lo, hi, acc2[h]);
        float v = lo + hi;
        v += __shfl_xor_sync(0xffffffffu, v, 1);
        v += __shfl_xor_sync(0xffffffffu, v, 2);
        if (q == 0) sS[r*NHs + h] = v + d_qbk[b*NHs + h] + mv;
      }
    }
    __syncthreads();

    // chunk-local softmax: 12 h x 16 threads, 4 s each
    if (t < 192){
      int h = t >> 4, l16 = t & 15;
      float v0 = sS[(l16   )*NHs + h], v1 = sS[(l16+16)*NHs + h];
      float v2 = sS[(l16+32)*NHs + h], v3 = sS[(l16+48)*NHs + h];
      float m = fmaxf(fmaxf(v0,v1), fmaxf(v2,v3));
      #pragma unroll
      for (int o = 1; o < 16; o <<= 1) m = fmaxf(m, __shfl_xor_sync(0xffffffffu, m, o));
      float e0 = expf(v0-m), e1 = expf(v1-m), e2 = expf(v2-m), e3 = expf(v3-m);
      float s = e0+e1+e2+e3;
      #pragma unroll
      for (int o = 1; o < 16; o <<= 1) s += __shfl_xor_sync(0xffffffffu, s, o);
      sS[(l16   )*NHs + h] = e0; sS[(l16+16)*NHs + h] = e1;
      sS[(l16+32)*NHs + h] = e2; sS[(l16+48)*NHs + h] = e3;
      if (l16 == 0){
        d_cmax[(b*NHs + h)*16 + sc] = m;
        d_csum[(b*NHs + h)*16 + sc] = s;
      }
    }
    __syncthreads();

    // fbar partial: i-slice per thread, f re-read from hot L2
    if (t < 192){
      ull acc2[2*NHs];
      #pragma unroll
      for (int k = 0; k < 2*NHs; k++) acc2[k] = 0ull;
      const float* fb = fbase + t*4;
      #pragma unroll 4
      for (int s = 0; s < 64; s++){
        ulonglong2 fv = *reinterpret_cast<const ulonglong2*>(fb + (size_t)s*Hsz);
        #pragma unroll
        for (int h = 0; h < NHs; h++){
          float e = sS[s*NHs + h];
          ull pp = pk2(e, e);
          acc2[2*h]   = ffma2(pp, fv.x, acc2[2*h]);
          acc2[2*h+1] = ffma2(pp, fv.y, acc2[2*h+1]);
        }
      }
      #pragma unroll
      for (int h = 0; h < NHs; h++){
        float4 o;
        upk2(o.x, o.y, acc2[2*h]);
        upk2(o.z, o.w, acc2[2*h+1]);
        *reinterpret_cast<float4*>(
          &d_fbp[((size_t)(sc*Bsz + b)*NHs + h)*Hsz + t*4]) = o;
      }
    }
  }
  gsync();

  // ---- P6': rescale+reduce fbar -> ctx partials via wv (W=72) ----
  if (bid < 72){
    int jc = bid % 6, ks = bid / 6;
    int j0 = jc*128, i0 = ks*64, h0 = jc*2;
    // weights w_sc/denom per (b, hl) computed by 32 threads into sS
    if (t < 32){
      int bb = t & 15, hl = t >> 4, h = h0 + hl;
      const float* cm = &d_cmax[(bb*NHs + h)*16];
      const float* cs = &d_csum[(bb*NHs + h)*16];
      float M = cm[0];
      #pragma unroll
      for (int sc = 1; sc < 16; sc++) M = fmaxf(M, cm[sc]);
      float wv_[16]; float den = 0.f;
      #pragma unroll
      for (int sc = 0; sc < 16; sc++){ wv_[sc] = expf(cm[sc]-M); den += cs[sc]*wv_[sc]; }
      float invd = 1.f/den;
      #pragma unroll
      for (int sc = 0; sc < 16; sc++) sS[(bb*2+hl)*16 + sc] = wv_[sc]*invd;
    }
    __syncthreads();
    #pragma unroll
    for (int k = 0; k < 8; k++){
      int v = t + 256*k;
      int bb = v>>7, hl = (v>>6)&1, i = v&63;
      int h = h0 + hl;
      float s = 0.f;
      #pragma unroll
      for (int sc = 0; sc < 16; sc++)
        s += d_fbp[((size_t)(sc*Bsz + bb)*NHs + h)*Hsz + i0 + i] * sS[(bb*2+hl)*16 + sc];
      sf[v] = s;
    }
    __syncthreads();
    int j = j0 + (t & 127), hl = (t & 127) >> 6, bh = t >> 7;
    float acc[8] = {0,0,0,0,0,0,0,0};
    #pragma unroll 4
    for (int i = 0; i < 64; i++){
      float w = wv[(size_t)(i0+i)*Hsz + j];
      #pragma unroll
      for (int bb = 0; bb < 8; bb++)
        acc[bb] = fmaf(sf[(bh*8+bb)*128 + hl*64 + i], w, acc[bb]);
    }
    #pragma unroll
    for (int bb = 0; bb < 8; bb++)
      d_ctxp[ks*(Bsz*Hsz) + (bh*8+bb)*Hsz + j] = acc[bb];
  }
  gsync();

  // ---- P7: y partials: (ctx+bv) @ wo[:,j], K-split 12 (W=72) ----
  if (bid < 72){
    int jc = bid % 6, ks = bid / 6;
    int j0 = jc*128, i0 = ks*64;
    #pragma unroll
    for (int k = 0; k < 4; k++){
      int v = t + 256*k;
      int bb = v>>6, i = v&63;
      float s = bv[i0 + i];
      #pragma unroll
      for (int p = 0; p < 12; p++)
        s += d_ctxp[p*(Bsz*Hsz) + bb*Hsz + i0 + i];
      sf[v] = s;
    }
    __syncthreads();
    int j = j0 + (t & 127), bh = t >> 7;
    float acc[8] = {0,0,0,0,0,0,0,0};
    #pragma unroll 4
    for (int i = 0; i < 64; i++){
      float w = wo[(size_t)(i0+i)*Hsz + j];
      #pragma unroll
      for (int bb = 0; bb < 8; bb++)
        acc[bb] = fmaf(sf[(bh*8+bb)*64 + i], w, acc[bb]);
    }
    #pragma unroll
    for (int bb = 0; bb < 8; bb++)
      d_yp[ks*(Bsz*Hsz) + (bh*8+bb)*Hsz + j] = acc[bb];
  }
  gsync();

  // ---- P8: LN1 (W=16) ----
  if (bid < 16){
    int b = bid;
    float yv[3];
    #pragma unroll
    for (int kk = 0; kk < 3; kk++){
      int j = t + 256*kk;
      float y = bo[j] + f[(size_t)b*Ssz*Hsz + j];
      #pragma unroll
      for (int ks = 0; ks < 12; ks++) y += d_yp[ks*(Bsz*Hsz) + b*Hsz + j];
      yv[kk] = y;
    }
    float mu = block_sum(yv[0]+yv[1]+yv[2], sred) * (1.f/Hsz);
    float ss = 0.f;
    #pragma unroll
    for (int kk = 0; kk < 3; kk++){ float d = yv[kk]-mu; ss += d*d; }
    float var = block_sum(ss, sred) * (1.f/Hsz);
    float inv = rsqrtf(var + 1e-12f);
    #pragma unroll
    for (int kk = 0; kk < 3; kk++){
      int j = t + 256*kk;
      d_attn0[b*Hsz + j] = (yv[kk]-mu) * inv * g1[j] + be1[j];
    }
  }
  gsync();

  // ---- P9: FFN1 partials, f32x2 b-pairs, K-split 16 (W=192) ----
  if (bid < 192){
    int mc = bid % 12, is = bid / 12;
    int m = mc*256 + t, i0 = is*48;
    for (int n = t; n < 8*48; n += 256){
      int bp = n / 48, i = n % 48;
      sbuf[n] = pk2(d_attn0[(2*bp)*Hsz + i0 + i], d_attn0[(2*bp+1)*Hsz + i0 + i]);
    }
    __syncthreads();
    ull acc2[8];
    #pragma unroll
    for (int k = 0; k < 8; k++) acc2[k] = 0ull;
    #pragma unroll 4
    for (int i = 0; i < 48; i++){
      float w = w1[(size_t)(i0+i)*FFs + m];
      ull wpk = pk2(w, w);
      #pragma unroll
      for (int bp = 0; bp < 8; bp++)
        acc2[bp] = ffma2(sbuf[bp*48 + i], wpk, acc2[bp]);
    }
    #pragma unroll
    for (int bp = 0; bp < 8; bp++){
      float lo, hi; upk2(lo, hi, acc2[bp]);
      d_gpart[(size_t)(is*Bsz + 2*bp)*FFs + m]   = lo;
      d_gpart[(size_t)(is*Bsz + 2*bp+1)*FFs + m] = hi;
    }
  }
  gsync();

  // ---- P10: reduce + bias + exact GELU (W=192) ----
  if (bid < 192){
    int n = bid*256 + t;
    float s = b1[n % FFs];
    #pragma unroll
    for (int is = 0; is < 16; is++) s += d_gpart[(size_t)is*(Bsz*FFs) + n];
    d_g[n] = 0.5f * s * (1.f + erff(s * 0.70710678118654752f));
  }
  gsync();

  // ---- P11: FFN2 partials, f32x2 b-pairs, K-split 24 (W=72) ----
  if (bid < 72){
    int jc = bid % 3, ms = bid / 3;
    int j = jc*256 + t, m0 = ms*128;
    #pragma unroll
    for (int k = 0; k < 4; k++){
      int n = t + 256*k;
      int bp = n >> 7, mm = n & 127;
      sbuf[n] = pk2(d_g[(2*bp)*FFs + m0 + mm], d_g[(2*bp+1)*FFs + m0 + mm]);
    }
    __syncthreads();
    ull acc2[8];
    #pragma unroll
    for (int k = 0; k < 8; k++) acc2[k] = 0ull;
    #pragma unroll 4
    for (int mm = 0; mm < 128; mm++){
      float w = w2[(size_t)(m0+mm)*Hsz + j];
      ull wpk = pk2(w, w);
      #pragma unroll
      for (int bp = 0; bp < 8; bp++)
        acc2[bp] = ffma2(sbuf[bp*128 + mm], wpk, acc2[bp]);
    }
    #pragma unroll
    for (int bp = 0; bp < 8; bp++){
      float lo, hi; upk2(lo, hi, acc2[bp]);
      d_opart[(size_t)(ms*Bsz + 2*bp)*Hsz + j]   = lo;
      d_opart[(size_t)(ms*Bsz + 2*bp+1)*Hsz + j] = hi;
    }
  }
  gsync();

  // ---- P12: LN2 (W=16) ----
  if (bid < 16){
    int b = bid;
    float yv[3];
    #pragma unroll
    for (int kk = 0; kk < 3; kk++){
      int j = t + 256*kk;
      float y = b2[j] + d_attn0[b*Hsz + j];
      #pragma unroll
      for (int ms = 0; ms < 24; ms++) y += d_opart[(size_t)(ms*Bsz + b)*Hsz + j];
      yv[kk] = y;
    }
    float mu = block_sum(yv[0]+yv[1]+yv[2], sred) * (1.f/Hsz);
    float ss = 0.f;
    #pragma unroll
    for (int kk = 0; kk < 3; kk++){ float d = yv[kk]-mu; ss += d*d; }
    float var = block_sum(ss, sred) * (1.f/Hsz);
    float inv = rsqrtf(var + 1e-12f);
    #pragma unroll
    for (int kk = 0; kk < 3; kk++){
      int j = t + 256*kk;
      d_hid[b*Hsz + j] = (yv[kk]-mu) * inv * g2[j] + be2[j];
    }
  }
  gsync();

  // ---- P13: pool partials: hid @ wp + bp, K-split 12 (W=72) ----
  if (bid < 72){
    int jc = bid % 6, ks = bid / 6;
    int j0 = jc*128, i0 = ks*64;
    #pragma unroll
    for (int k = 0; k < 4; k++){
      int v = t + 256*k;
      sf[v] = d_hid[(v>>6)*Hsz + i0 + (v&63)];
    }
    __syncthreads();
    int j = j0 + (t & 127), bh = t >> 7;
    float binit = (ks == 0) ? bp[j] : 0.f;
    float acc[8];
    #pragma unroll
    for (int bb = 0; bb < 8; bb++) acc[bb] = binit;
    #pragma unroll 4
    for (int i = 0; i < 64; i++){
      float w = wp[(size_t)(i0+i)*Hsz + j];
      #pragma unroll
      for (int bb = 0; bb < 8; bb++)
        acc[bb] = fmaf(sf[(bh*8+bb)*64 + i], w, acc[bb]);
    }
    #pragma unroll
    for (int bb = 0; bb < 8; bb++)
      d_pp[ks*(Bsz*Hsz) + (bh*8+bb)*Hsz + j] = acc[bb];
  }
  gsync();

  // ---- P14: pooled = tanh(.), cls = pooled @ wm + bm (W=16) ----
  if (bid < 16){
    int b = bid;
    float contrib = 0.f;
    #pragma unroll
    for (int kk = 0; kk < 3; kk++){
      int j = t + 256*kk;
      float y = 0.f;
      #pragma unroll
      for (int ks = 0; ks < 12; ks++) y += d_pp[ks*(Bsz*Hsz) + b*Hsz + j];
      contrib += tanhf(y) * wm[j];
    }
    float c = block_sum(contrib, sred);
    if (t == 0) out[b] = c + bm[0];
  }
}

// ---------------- launch ----------------
extern "C" void kernel_launch(void* const* d_in, const int* in_sizes, int n_in,
                              void* d_out, int out_size){
  (void)in_sizes; (void)n_in; (void)out_size;
  bert_head<<<NB, NT>>>(
    (const float*)d_in[0],  (const float*)d_in[1],
    (const float*)d_in[2],  (const float*)d_in[3],
    (const float*)d_in[4],  (const float*)d_in[5],
    (const float*)d_in[6],  (const float*)d_in[7],
    (const float*)d_in[8],  (const float*)d_in[9],
    (const float*)d_in[10], (const float*)d_in[11],
    (const float*)d_in[12], (const float*)d_in[13],
    (const float*)d_in[14], (const float*)d_in[15],
    (const float*)d_in[16], (const float*)d_in[17],
    (const float*)d_in[18], (const float*)d_in[19],
    (const float*)d_in[20], (const float*)d_in[21],
    (float*)d_out);
}